// round 1
// baseline (speedup 1.0000x reference)
#include <cuda_runtime.h>
#include <math.h>

#define TT 2048
#define DD 768
#define NH 12
#define DHH 64

// ---------------- scratch (device globals, no allocation) ----------------
__device__ float g_xn[TT * DD];            // ln1(x)
__device__ float g_qkv[TT * 3 * DD];       // qkv projections
__device__ float g_geov[TT * DD];          // geo_v
__device__ float g_rl[TT * NH * 6];        // read lines (normalized)
__device__ float g_jw[TT * NH * 6];        // J @ write lines
__device__ float g_gate[TT];               // gate scalar per token
__device__ float g_comb[TT * DD];          // combined attention output
__device__ float g_h[TT * DD];             // h = x + attn
__device__ float g_m[TT * DD];             // ln2(h)
__device__ float g_act[TT * 4 * DD];       // gelu(fc)

// ---------------- LayerNorm ----------------
__global__ void ln_kernel(const float* __restrict__ x, const float* __restrict__ g,
                          const float* __restrict__ b, float* __restrict__ y)
{
    const int t = blockIdx.x, tid = threadIdx.x;
    const float* xr = x + (size_t)t * DD;
    float v[3];
    float s = 0.f, s2 = 0.f;
#pragma unroll
    for (int i = 0; i < 3; ++i) {
        v[i] = xr[tid + i * 256];
        s += v[i];
        s2 += v[i] * v[i];
    }
    __shared__ float rs[8], rs2[8];
#pragma unroll
    for (int o = 16; o > 0; o >>= 1) {
        s  += __shfl_xor_sync(0xffffffffu, s, o);
        s2 += __shfl_xor_sync(0xffffffffu, s2, o);
    }
    const int w = tid >> 5, l = tid & 31;
    if (l == 0) { rs[w] = s; rs2[w] = s2; }
    __syncthreads();
    s = 0.f; s2 = 0.f;
#pragma unroll
    for (int i = 0; i < 8; ++i) { s += rs[i]; s2 += rs2[i]; }
    const float mean = s * (1.f / 768.f);
    const float var  = s2 * (1.f / 768.f) - mean * mean;
    const float rstd = rsqrtf(var + 1e-5f);
#pragma unroll
    for (int i = 0; i < 3; ++i) {
        const int c = tid + i * 256;
        y[(size_t)t * DD + c] = (v[i] - mean) * rstd * g[c] + b[c];
    }
}

// ---------------- generic SGEMM 64x64x16, 256 thr, 4x4/thread ----------------
__device__ __forceinline__ float gelu_f(float x)
{
    const float x3 = x * x * x;
    return 0.5f * x * (1.f + tanhf(0.7978845608028654f * (x + 0.044715f * x3)));
}

template <bool GELU, bool RES>
__global__ void sgemm_kernel(const float* __restrict__ A, const float* __restrict__ B,
                             const float* __restrict__ bias, const float* __restrict__ R,
                             float* __restrict__ C, int M, int N, int K)
{
    __shared__ float As[16][68];   // A^T tile (k-major), padded
    __shared__ float Bs[16][64];
    const int tid = threadIdx.x;
    const int tx = tid & 15, ty = tid >> 4;
    const int m0 = blockIdx.y * 64, n0 = blockIdx.x * 64;
    const int lm = tid >> 2, lk = (tid & 3) * 4;
    const int bk = tid >> 4, bn = (tid & 15) * 4;
    const float* Ap = A + (size_t)(m0 + lm) * K + lk;
    const float* Bp = B + (size_t)bk * N + n0 + bn;
    float acc[4][4] = {};

    for (int kt = 0; kt < K; kt += 16) {
        float4 a = *(const float4*)(Ap + kt);
        float4 b = *(const float4*)(Bp + (size_t)kt * N);
        As[lk + 0][lm] = a.x; As[lk + 1][lm] = a.y;
        As[lk + 2][lm] = a.z; As[lk + 3][lm] = a.w;
        *(float4*)&Bs[bk][bn] = b;
        __syncthreads();
#pragma unroll
        for (int k = 0; k < 16; ++k) {
            float4 av = *(const float4*)&As[k][ty * 4];
            float4 bv = *(const float4*)&Bs[k][tx * 4];
            acc[0][0] += av.x * bv.x; acc[0][1] += av.x * bv.y; acc[0][2] += av.x * bv.z; acc[0][3] += av.x * bv.w;
            acc[1][0] += av.y * bv.x; acc[1][1] += av.y * bv.y; acc[1][2] += av.y * bv.z; acc[1][3] += av.y * bv.w;
            acc[2][0] += av.z * bv.x; acc[2][1] += av.z * bv.y; acc[2][2] += av.z * bv.z; acc[2][3] += av.z * bv.w;
            acc[3][0] += av.w * bv.x; acc[3][1] += av.w * bv.y; acc[3][2] += av.w * bv.z; acc[3][3] += av.w * bv.w;
        }
        __syncthreads();
    }

    const int c = n0 + tx * 4;
    const float4 bv = *(const float4*)&bias[c];
#pragma unroll
    for (int i = 0; i < 4; ++i) {
        const int r = m0 + ty * 4 + i;
        float4 o;
        o.x = acc[i][0] + bv.x; o.y = acc[i][1] + bv.y;
        o.z = acc[i][2] + bv.z; o.w = acc[i][3] + bv.w;
        if (GELU) { o.x = gelu_f(o.x); o.y = gelu_f(o.y); o.z = gelu_f(o.z); o.w = gelu_f(o.w); }
        if (RES) {
            const float4 rv = *(const float4*)&R[(size_t)r * N + c];
            o.x += rv.x; o.y += rv.y; o.z += rv.z; o.w += rv.w;
        }
        *(float4*)&C[(size_t)r * N + c] = o;
    }
}

// ---------------- small projections + exterior/Plucker lines + gate ----------------
__device__ __forceinline__ void ext6(const float* p, const float* q, float* L)
{
    L[0] = p[0] * q[1] - p[1] * q[0];
    L[1] = p[0] * q[2] - p[2] * q[0];
    L[2] = p[0] * q[3] - p[3] * q[0];
    L[3] = p[1] * q[2] - p[2] * q[1];
    L[4] = p[1] * q[3] - p[3] * q[1];
    L[5] = p[2] * q[3] - p[3] * q[2];
    float n2 = 0.f;
#pragma unroll
    for (int i = 0; i < 6; ++i) n2 += L[i] * L[i];
    float n = fmaxf(sqrtf(n2), 1e-12f);
    const float inv = 1.f / n;
#pragma unroll
    for (int i = 0; i < 6; ++i) L[i] *= inv;
}

__global__ void smallproj_kernel(const float* __restrict__ xn,
                                 const float* __restrict__ w1w, const float* __restrict__ w2w,
                                 const float* __restrict__ w1r, const float* __restrict__ w2r,
                                 const float* __restrict__ gw, const float* __restrict__ gb,
                                 float* __restrict__ rlo, float* __restrict__ jwo,
                                 float* __restrict__ gateo)
{
    const int t = blockIdx.x, tid = threadIdx.x;
    __shared__ float sx[768], sxp[768], so[204];
#pragma unroll
    for (int i = 0; i < 3; ++i) {
        const int c = tid + i * 256;
        sx[c]  = xn[(size_t)t * DD + c];
        sxp[c] = (t == 0) ? 0.f : xn[(size_t)(t - 1) * DD + c];
    }
    __syncthreads();
    if (tid < 204) {
        const float* w; const float* xv; int c, st;
        if (tid < 48)       { w = w1w; c = tid;       xv = sxp; st = 48; }
        else if (tid < 96)  { w = w2w; c = tid - 48;  xv = sx;  st = 48; }
        else if (tid < 144) { w = w1r; c = tid - 96;  xv = sx;  st = 48; }
        else if (tid < 192) { w = w2r; c = tid - 144; xv = sx;  st = 48; }
        else                { w = gw;  c = tid - 192; xv = sx;  st = 12; }
        float acc = 0.f;
        for (int k = 0; k < 768; ++k) acc += xv[k] * w[(size_t)k * st + c];
        so[tid] = acc;
    }
    __syncthreads();
    if (tid < NH) {
        const int h = tid;
        float p1[4], p2[4], L[6];
#pragma unroll
        for (int e = 0; e < 4; ++e) { p1[e] = so[h * 4 + e]; p2[e] = so[48 + h * 4 + e]; }
        ext6(p1, p2, L);
        const size_t base = (size_t)t * (NH * 6) + h * 6;
        // J_write = wl @ J6 = (L5, -L4, L3, L2, -L1, L0)
        jwo[base + 0] =  L[5]; jwo[base + 1] = -L[4]; jwo[base + 2] =  L[3];
        jwo[base + 3] =  L[2]; jwo[base + 4] = -L[1]; jwo[base + 5] =  L[0];
#pragma unroll
        for (int e = 0; e < 4; ++e) { p1[e] = so[96 + h * 4 + e]; p2[e] = so[144 + h * 4 + e]; }
        ext6(p1, p2, L);
#pragma unroll
        for (int i = 0; i < 6; ++i) rlo[base + i] = L[i];
    }
    if (tid == 0) {
        float acc = 0.f;
#pragma unroll
        for (int h = 0; h < NH; ++h) acc += 1.f / (1.f + expf(-(so[192 + h] + gb[h])));
        gateo[t] = acc * (1.f / 12.f);
    }
}

// ---------------- fused dual-path causal flash attention ----------------
// grid (32, 12): 64-query tile x head. 256 threads = 16x16, 4x4 per thread.
#define ALDS 68

#define SOFTMAX_UPDATE(Sv, Mv, Lv, Ov)                                             \
    {                                                                              \
        _Pragma("unroll")                                                          \
        for (int i = 0; i < 4; ++i) {                                              \
            float mx = fmaxf(fmaxf(Sv[i][0], Sv[i][1]), fmaxf(Sv[i][2], Sv[i][3]));\
            _Pragma("unroll")                                                      \
            for (int o = 8; o > 0; o >>= 1)                                        \
                mx = fmaxf(mx, __shfl_xor_sync(0xffffffffu, mx, o));               \
            const float mn = fmaxf(Mv[i], mx);                                     \
            const float corr = __expf(Mv[i] - mn);                                 \
            Mv[i] = mn;                                                            \
            float rsum = 0.f;                                                      \
            _Pragma("unroll")                                                      \
            for (int j = 0; j < 4; ++j) { Sv[i][j] = __expf(Sv[i][j] - mn); rsum += Sv[i][j]; } \
            _Pragma("unroll")                                                      \
            for (int o = 8; o > 0; o >>= 1)                                        \
                rsum += __shfl_xor_sync(0xffffffffu, rsum, o);                     \
            Lv[i] = Lv[i] * corr + rsum;                                           \
            _Pragma("unroll")                                                      \
            for (int j = 0; j < 4; ++j) Ov[i][j] *= corr;                          \
            *(float4*)&sP[(ty * 4 + i) * ALDS + tx * 4] =                          \
                make_float4(Sv[i][0], Sv[i][1], Sv[i][2], Sv[i][3]);               \
        }                                                                          \
    }

#define PV_ACC(Ov, SVt)                                                            \
    {                                                                              \
        _Pragma("unroll")                                                          \
        for (int s4 = 0; s4 < 16; ++s4) {                                          \
            float4 p[4], vv[4];                                                    \
            _Pragma("unroll")                                                      \
            for (int i = 0; i < 4; ++i) p[i] = *(const float4*)&sP[(ty * 4 + i) * ALDS + 4 * s4]; \
            _Pragma("unroll")                                                      \
            for (int j = 0; j < 4; ++j) vv[j] = *(const float4*)&SVt[(tx * 4 + j) * ALDS + 4 * s4]; \
            _Pragma("unroll")                                                      \
            for (int i = 0; i < 4; ++i) {                                          \
                _Pragma("unroll")                                                  \
                for (int j = 0; j < 4; ++j)                                        \
                    Ov[i][j] += p[i].x * vv[j].x + p[i].y * vv[j].y +              \
                                p[i].z * vv[j].z + p[i].w * vv[j].w;               \
            }                                                                      \
        }                                                                          \
    }

__global__ void attn_kernel(const float* __restrict__ qkv, const float* __restrict__ geov,
                            const float* __restrict__ rl, const float* __restrict__ jwg,
                            const float* __restrict__ gate, const float* __restrict__ inc,
                            float* __restrict__ comb)
{
    extern __shared__ float smem_f[];
    float* sQ   = smem_f;                  // 64*68
    float* sK   = sQ + 64 * ALDS;          // 64*68
    float* sVt  = sK + 64 * ALDS;          // 64*68 (transposed: [d][s])
    float* sGVt = sVt + 64 * ALDS;         // 64*68
    float* sP   = sGVt + 64 * ALDS;        // 64*68
    float* sRL  = sP + 64 * ALDS;          // 64*8
    float* sJWt = sRL + 64 * 8;            // 6*68 (transposed: [i][s])

    const int h = blockIdx.y;
    const int qb = gridDim.x - 1 - blockIdx.x;   // heavy tiles first
    const int qt0 = qb * 64;
    const int tid = threadIdx.x;
    const int tx = tid & 15, ty = tid >> 4;
    const int lr = tid >> 2;            // loader row 0..63
    const int ld0 = (tid & 3) * 16;     // 0,16,32,48

    { // load Q tile
        const float* src = qkv + (size_t)(qt0 + lr) * (3 * DD) + h * DHH + ld0;
#pragma unroll
        for (int u = 0; u < 4; ++u)
            *(float4*)&sQ[lr * ALDS + ld0 + 4 * u] = *(const float4*)(src + 4 * u);
    }
    if (tid < 64) {
#pragma unroll
        for (int i = 0; i < 6; ++i)
            sRL[tid * 8 + i] = rl[(size_t)(qt0 + tid) * (NH * 6) + h * 6 + i];
    }
    const float iscale = inc[h];

    float Os[4][4] = {}, Og[4][4] = {};
    float ms[4], ls[4], mg[4], lg[4];
#pragma unroll
    for (int i = 0; i < 4; ++i) { ms[i] = -1e30f; mg[i] = -1e30f; ls[i] = 0.f; lg[i] = 0.f; }

    for (int kt0 = 0; kt0 <= qt0; kt0 += 64) {
        __syncthreads();   // guard previous tile reads + Q/RL staging
        { // load K (natural), V/GV (transposed), JW (transposed)
            const float* ksrc = qkv  + (size_t)(kt0 + lr) * (3 * DD) +     DD + h * DHH + ld0;
            const float* vsrc = qkv  + (size_t)(kt0 + lr) * (3 * DD) + 2 * DD + h * DHH + ld0;
            const float* gsrc = geov + (size_t)(kt0 + lr) * DD + h * DHH + ld0;
#pragma unroll
            for (int u = 0; u < 4; ++u) {
                *(float4*)&sK[lr * ALDS + ld0 + 4 * u] = *(const float4*)(ksrc + 4 * u);
                const int dd = ld0 + 4 * u;
                float4 vv = *(const float4*)(vsrc + 4 * u);
                sVt[(dd + 0) * ALDS + lr] = vv.x; sVt[(dd + 1) * ALDS + lr] = vv.y;
                sVt[(dd + 2) * ALDS + lr] = vv.z; sVt[(dd + 3) * ALDS + lr] = vv.w;
                float4 gv = *(const float4*)(gsrc + 4 * u);
                sGVt[(dd + 0) * ALDS + lr] = gv.x; sGVt[(dd + 1) * ALDS + lr] = gv.y;
                sGVt[(dd + 2) * ALDS + lr] = gv.z; sGVt[(dd + 3) * ALDS + lr] = gv.w;
            }
        }
        if (tid < 64) {
#pragma unroll
            for (int i = 0; i < 6; ++i)
                sJWt[i * ALDS + tid] = jwg[(size_t)(kt0 + tid) * (NH * 6) + h * 6 + i];
        }
        __syncthreads();

        const bool diag = (kt0 == qt0);

        // ---- standard path logits: S = Q K^T * scale ----
        float s[4][4] = {};
#pragma unroll
        for (int d4 = 0; d4 < 16; ++d4) {
            float4 a[4], b[4];
#pragma unroll
            for (int i = 0; i < 4; ++i) a[i] = *(const float4*)&sQ[(ty * 4 + i) * ALDS + 4 * d4];
#pragma unroll
            for (int j = 0; j < 4; ++j) b[j] = *(const float4*)&sK[(tx * 4 + j) * ALDS + 4 * d4];
#pragma unroll
            for (int i = 0; i < 4; ++i)
#pragma unroll
                for (int j = 0; j < 4; ++j)
                    s[i][j] += a[i].x * b[j].x + a[i].y * b[j].y + a[i].z * b[j].z + a[i].w * b[j].w;
        }
#pragma unroll
        for (int i = 0; i < 4; ++i)
#pragma unroll
            for (int j = 0; j < 4; ++j) {
                s[i][j] *= 0.125f;
                if (diag && (tx * 4 + j > ty * 4 + i)) s[i][j] = -1e30f;
            }
        SOFTMAX_UPDATE(s, ms, ls, Os)
        __syncthreads();
        PV_ACC(Os, sVt)
        __syncthreads();

        // ---- geometric path logits: S = RL . JW * inc_scale ----
#pragma unroll
        for (int i = 0; i < 4; ++i)
#pragma unroll
            for (int j = 0; j < 4; ++j) s[i][j] = 0.f;
#pragma unroll
        for (int i6 = 0; i6 < 6; ++i6) {
            float ra[4];
#pragma unroll
            for (int i = 0; i < 4; ++i) ra[i] = sRL[(ty * 4 + i) * 8 + i6];
            const float4 jb = *(const float4*)&sJWt[i6 * ALDS + tx * 4];
#pragma unroll
            for (int i = 0; i < 4; ++i) {
                s[i][0] += ra[i] * jb.x; s[i][1] += ra[i] * jb.y;
                s[i][2] += ra[i] * jb.z; s[i][3] += ra[i] * jb.w;
            }
        }
#pragma unroll
        for (int i = 0; i < 4; ++i)
#pragma unroll
            for (int j = 0; j < 4; ++j) {
                s[i][j] *= iscale;
                if (diag && (tx * 4 + j > ty * 4 + i)) s[i][j] = -1e30f;
            }
        SOFTMAX_UPDATE(s, mg, lg, Og)
        __syncthreads();
        PV_ACC(Og, sGVt)
        // loop-top sync guards sP/sK/sVt reuse
    }

    // ---- finalize: combined = (1-g)*std + g*geo ----
#pragma unroll
    for (int i = 0; i < 4; ++i) {
        const int t = qt0 + ty * 4 + i;
        const float g = gate[t];
        const float is = (1.f - g) / ls[i];
        const float ig = g / lg[i];
        float4 o;
        o.x = Os[i][0] * is + Og[i][0] * ig;
        o.y = Os[i][1] * is + Og[i][1] * ig;
        o.z = Os[i][2] * is + Og[i][2] * ig;
        o.w = Os[i][3] * is + Og[i][3] * ig;
        *(float4*)&comb[(size_t)t * DD + h * DHH + tx * 4] = o;
    }
}

// ---------------- host ----------------
extern "C" void kernel_launch(void* const* d_in, const int* in_sizes, int n_in,
                              void* d_out, int out_size)
{
    (void)in_sizes; (void)n_in; (void)out_size;
    const float* x     = (const float*)d_in[0];
    const float* ln1g  = (const float*)d_in[1];
    const float* ln1b  = (const float*)d_in[2];
    const float* qkvw  = (const float*)d_in[3];
    const float* qkvb  = (const float*)d_in[4];
    const float* w1w   = (const float*)d_in[5];
    const float* w2w   = (const float*)d_in[6];
    const float* w1r   = (const float*)d_in[7];
    const float* w2r   = (const float*)d_in[8];
    const float* geovw = (const float*)d_in[9];
    const float* geovb = (const float*)d_in[10];
    const float* gatew = (const float*)d_in[11];
    const float* gateb = (const float*)d_in[12];
    const float* incs  = (const float*)d_in[13];
    const float* outw  = (const float*)d_in[14];
    const float* outb  = (const float*)d_in[15];
    const float* ln2g  = (const float*)d_in[16];
    const float* ln2b  = (const float*)d_in[17];
    const float* fcw   = (const float*)d_in[18];
    const float* fcb   = (const float*)d_in[19];
    const float* projw = (const float*)d_in[20];
    const float* projb = (const float*)d_in[21];
    float* out = (float*)d_out;

    float *xn, *qkv, *geov, *rlp, *jwp, *gatep, *combp, *hp, *mp, *actp;
    cudaGetSymbolAddress((void**)&xn,    g_xn);
    cudaGetSymbolAddress((void**)&qkv,   g_qkv);
    cudaGetSymbolAddress((void**)&geov,  g_geov);
    cudaGetSymbolAddress((void**)&rlp,   g_rl);
    cudaGetSymbolAddress((void**)&jwp,   g_jw);
    cudaGetSymbolAddress((void**)&gatep, g_gate);
    cudaGetSymbolAddress((void**)&combp, g_comb);
    cudaGetSymbolAddress((void**)&hp,    g_h);
    cudaGetSymbolAddress((void**)&mp,    g_m);
    cudaGetSymbolAddress((void**)&actp,  g_act);

    const int smem_attn = (5 * 64 * ALDS + 64 * 8 + 6 * ALDS) * (int)sizeof(float);
    cudaFuncSetAttribute(attn_kernel, cudaFuncAttributeMaxDynamicSharedMemorySize, smem_attn);

    // 1. xn = LN1(x)
    ln_kernel<<<TT, 256>>>(x, ln1g, ln1b, xn);
    // 2. qkv = xn @ qkv_w + b
    sgemm_kernel<false, false><<<dim3(36, 32), 256>>>(xn, qkvw, qkvb, nullptr, qkv, TT, 3 * DD, DD);
    // 3. geo_v = xn @ geo_v_w + b
    sgemm_kernel<false, false><<<dim3(12, 32), 256>>>(xn, geovw, geovb, nullptr, geov, TT, DD, DD);
    // 4. line projections + exterior + J + gate
    smallproj_kernel<<<TT, 256>>>(xn, w1w, w2w, w1r, w2r, gatew, gateb, rlp, jwp, gatep);
    // 5. fused dual-path attention -> combined
    attn_kernel<<<dim3(32, NH), 256, smem_attn>>>(qkv, geov, rlp, jwp, gatep, incs, combp);
    // 6. h = x + combined @ out_w + b
    sgemm_kernel<false, true><<<dim3(12, 32), 256>>>(combp, outw, outb, x, hp, TT, DD, DD);
    // 7. m = LN2(h)
    ln_kernel<<<TT, 256>>>(hp, ln2g, ln2b, mp);
    // 8. act = gelu(m @ fc_w + b)
    sgemm_kernel<true, false><<<dim3(48, 32), 256>>>(mp, fcw, fcb, nullptr, actp, TT, 4 * DD, DD);
    // 9. out = h + act @ proj_w + b
    sgemm_kernel<false, true><<<dim3(12, 32), 256>>>(actp, projw, projb, hp, out, TT, DD, 4 * DD);
}

// round 3
// speedup vs baseline: 1.1812x; 1.1812x over previous
#include <cuda_runtime.h>
#include <math.h>
#include <stdint.h>

#define TT 2048
#define DD 768
#define NH 12
#define DHH 64

// ---------------- scratch (device globals, no allocation) ----------------
__device__ float g_xn[TT * DD];            // ln1(x)
__device__ float g_qkv[TT * 3 * DD];       // qkv projections
__device__ float g_geov[TT * DD];          // geo_v
__device__ float g_wcat[DD * 256];         // packed small-proj weights (padded)
__device__ float g_P[TT * 256];            // small projections output
__device__ float g_zbias[256];             // zeros (device globals zero-init)
__device__ float g_rl[TT * NH * 6];        // read lines (normalized)
__device__ float g_jw[TT * NH * 6];        // J @ write lines
__device__ float g_gate[TT];               // gate scalar per token
__device__ float g_comb[TT * DD];          // combined attention output
__device__ float g_h[TT * DD];             // h = x + attn
__device__ float g_m[TT * DD];             // ln2(h)
__device__ float g_act[TT * 4 * DD];       // gelu(fc)

// ---------------- helpers ----------------
__device__ __forceinline__ uint32_t f2tf32(float x)
{
    uint32_t r;
    asm("cvt.rna.tf32.f32 %0, %1;" : "=r"(r) : "f"(x));
    return r;
}

__device__ __forceinline__ float gelu_f(float x)
{
    const float x3 = x * x * x;
    return 0.5f * x * (1.f + tanhf(0.7978845608028654f * (x + 0.044715f * x3)));
}

// ---------------- LayerNorm ----------------
__global__ void ln_kernel(const float* __restrict__ x, const float* __restrict__ g,
                          const float* __restrict__ b, float* __restrict__ y)
{
    const int t = blockIdx.x, tid = threadIdx.x;
    const float* xr = x + (size_t)t * DD;
    float v[3];
    float s = 0.f, s2 = 0.f;
#pragma unroll
    for (int i = 0; i < 3; ++i) {
        v[i] = xr[tid + i * 256];
        s += v[i];
        s2 += v[i] * v[i];
    }
    __shared__ float rs[8], rs2[8];
#pragma unroll
    for (int o = 16; o > 0; o >>= 1) {
        s  += __shfl_xor_sync(0xffffffffu, s, o);
        s2 += __shfl_xor_sync(0xffffffffu, s2, o);
    }
    const int w = tid >> 5, l = tid & 31;
    if (l == 0) { rs[w] = s; rs2[w] = s2; }
    __syncthreads();
    s = 0.f; s2 = 0.f;
#pragma unroll
    for (int i = 0; i < 8; ++i) { s += rs[i]; s2 += rs2[i]; }
    const float mean = s * (1.f / 768.f);
    const float var  = s2 * (1.f / 768.f) - mean * mean;
    const float rstd = rsqrtf(var + 1e-5f);
#pragma unroll
    for (int i = 0; i < 3; ++i) {
        const int c = tid + i * 256;
        y[(size_t)t * DD + c] = (v[i] - mean) * rstd * g[c] + b[c];
    }
}

// ---------------- tf32 tensor-core GEMM: 128x128x16, 256 thr, 8 warps ----------------
// A[M,K] row-major, B[K,N] row-major, C = A@B + bias (+GELU) (+R residual)
#define SPAD 136

#define MMA_TF32(d, a, b)                                                      \
    asm volatile("mma.sync.aligned.m16n8k8.row.col.f32.tf32.tf32.f32 "         \
                 "{%0,%1,%2,%3}, {%4,%5,%6,%7}, {%8,%9}, {%0,%1,%2,%3};"       \
                 : "+f"(d[0]), "+f"(d[1]), "+f"(d[2]), "+f"(d[3])              \
                 : "r"(a[0]), "r"(a[1]), "r"(a[2]), "r"(a[3]),                 \
                   "r"(b[0]), "r"(b[1]))

#define LOAD_TILE(ktof, buf)                                                   \
    {                                                                          \
        _Pragma("unroll")                                                      \
        for (int hh = 0; hh < 2; ++hh) {                                       \
            float4 v = *(const float4*)(Aglob + (ktof) + hh * 8);              \
            const int kc = acol4 * 4 + hh * 8;                                 \
            As[buf][(kc + 0) * SPAD + arow] = f2tf32(v.x);                     \
            As[buf][(kc + 1) * SPAD + arow] = f2tf32(v.y);                     \
            As[buf][(kc + 2) * SPAD + arow] = f2tf32(v.z);                     \
            As[buf][(kc + 3) * SPAD + arow] = f2tf32(v.w);                     \
        }                                                                      \
        _Pragma("unroll")                                                      \
        for (int hh = 0; hh < 2; ++hh) {                                       \
            float4 v = *(const float4*)(Bglob + (size_t)(ktof) * N + hh * 64); \
            const int nc = bn4 * 4 + hh * 64;                                  \
            Bs[buf][bk * SPAD + nc + 0] = f2tf32(v.x);                         \
            Bs[buf][bk * SPAD + nc + 1] = f2tf32(v.y);                         \
            Bs[buf][bk * SPAD + nc + 2] = f2tf32(v.z);                         \
            Bs[buf][bk * SPAD + nc + 3] = f2tf32(v.w);                         \
        }                                                                      \
    }

#define COMPUTE_TILE(buf)                                                      \
    {                                                                          \
        _Pragma("unroll")                                                      \
        for (int ks = 0; ks < 2; ++ks) {                                       \
            const int kb = ks * 8 + (lane & 3);                                \
            uint32_t a[2][4], b[8][2];                                         \
            _Pragma("unroll")                                                  \
            for (int mi = 0; mi < 2; ++mi) {                                   \
                const int r = warpM + mi * 16 + (lane >> 2);                   \
                a[mi][0] = As[buf][kb * SPAD + r];                             \
                a[mi][1] = As[buf][kb * SPAD + r + 8];                         \
                a[mi][2] = As[buf][(kb + 4) * SPAD + r];                       \
                a[mi][3] = As[buf][(kb + 4) * SPAD + r + 8];                   \
            }                                                                  \
            _Pragma("unroll")                                                  \
            for (int ni = 0; ni < 8; ++ni) {                                   \
                const int c = warpN + ni * 8 + (lane >> 2);                    \
                b[ni][0] = Bs[buf][kb * SPAD + c];                             \
                b[ni][1] = Bs[buf][(kb + 4) * SPAD + c];                       \
            }                                                                  \
            _Pragma("unroll")                                                  \
            for (int mi = 0; mi < 2; ++mi)                                     \
                _Pragma("unroll")                                              \
                for (int ni = 0; ni < 8; ++ni)                                 \
                    MMA_TF32(acc[mi][ni], a[mi], b[ni]);                       \
        }                                                                      \
    }

template <bool GELU, bool RES>
__global__ __launch_bounds__(256) void gemm_tf32(const float* __restrict__ A,
                                                 const float* __restrict__ B,
                                                 const float* __restrict__ bias,
                                                 const float* __restrict__ R,
                                                 float* __restrict__ C,
                                                 int M, int N, int K)
{
    __shared__ uint32_t As[2][16 * SPAD];
    __shared__ uint32_t Bs[2][16 * SPAD];
    const int tid = threadIdx.x, lane = tid & 31, w = tid >> 5;
    const int warpM = (w & 3) * 32, warpN = (w >> 2) * 64;
    const int m0 = blockIdx.y * 128, n0 = blockIdx.x * 128;
    const int arow = tid & 127, acol4 = tid >> 7;     // A loader
    const int bk = tid >> 4,   bn4 = tid & 15;        // B loader
    const float* Aglob = A + (size_t)(m0 + arow) * K + acol4 * 4;
    const float* Bglob = B + (size_t)bk * N + n0 + bn4 * 4;

    float acc[2][8][4] = {};

    LOAD_TILE(0, 0);
    __syncthreads();
    const int ntiles = K >> 4;
    for (int kt = 0; kt < ntiles; ++kt) {
        const int buf = kt & 1;
        if (kt + 1 < ntiles) LOAD_TILE((kt + 1) * 16, buf ^ 1);
        COMPUTE_TILE(buf);
        __syncthreads();
    }

    // epilogue
#pragma unroll
    for (int mi = 0; mi < 2; ++mi) {
#pragma unroll
        for (int ni = 0; ni < 8; ++ni) {
            const int col = n0 + warpN + ni * 8 + 2 * (lane & 3);
            const float b0 = bias[col], b1 = bias[col + 1];
#pragma unroll
            for (int r = 0; r < 2; ++r) {
                const int row = m0 + warpM + mi * 16 + (lane >> 2) + 8 * r;
                float o0 = acc[mi][ni][2 * r + 0] + b0;
                float o1 = acc[mi][ni][2 * r + 1] + b1;
                if (GELU) { o0 = gelu_f(o0); o1 = gelu_f(o1); }
                if (RES) {
                    o0 += R[(size_t)row * N + col];
                    o1 += R[(size_t)row * N + col + 1];
                }
                float2 ov = make_float2(o0, o1);
                *(float2*)&C[(size_t)row * N + col] = ov;
            }
        }
    }
}

// ---------------- pack small-proj weights into [768, 256] ----------------
__global__ void pack_w_kernel(const float* __restrict__ w1w, const float* __restrict__ w2w,
                              const float* __restrict__ w1r, const float* __restrict__ w2r,
                              const float* __restrict__ gw, float* __restrict__ Wcat)
{
    const int idx = blockIdx.x * 256 + threadIdx.x;
    if (idx >= DD * 256) return;
    const int k = idx >> 8, c = idx & 255;
    float v = 0.f;
    if (c < 48)       v = w1w[k * 48 + c];
    else if (c < 96)  v = w2w[k * 48 + c - 48];
    else if (c < 144) v = w1r[k * 48 + c - 96];
    else if (c < 192) v = w2r[k * 48 + c - 144];
    else if (c < 204) v = gw[k * 12 + c - 192];
    Wcat[idx] = v;
}

// ---------------- exterior lines + J map + gate from P ----------------
__device__ __forceinline__ void ext6(const float* p, const float* q, float* L)
{
    L[0] = p[0] * q[1] - p[1] * q[0];
    L[1] = p[0] * q[2] - p[2] * q[0];
    L[2] = p[0] * q[3] - p[3] * q[0];
    L[3] = p[1] * q[2] - p[2] * q[1];
    L[4] = p[1] * q[3] - p[3] * q[1];
    L[5] = p[2] * q[3] - p[3] * q[2];
    float n2 = 0.f;
#pragma unroll
    for (int i = 0; i < 6; ++i) n2 += L[i] * L[i];
    const float inv = 1.f / fmaxf(sqrtf(n2), 1e-12f);
#pragma unroll
    for (int i = 0; i < 6; ++i) L[i] *= inv;
}

__global__ void lines_kernel(const float* __restrict__ P, const float* __restrict__ gb,
                             float* __restrict__ rlo, float* __restrict__ jwo,
                             float* __restrict__ gateo)
{
    const int idx = blockIdx.x * 256 + threadIdx.x;
    if (idx >= TT * NH) return;
    const int t = idx / NH, h = idx % NH;
    const float* Pt = P + (size_t)t * 256;
    float p1[4], p2[4], L[6];
#pragma unroll
    for (int e = 0; e < 4; ++e) {
        p1[e] = (t > 0) ? P[(size_t)(t - 1) * 256 + h * 4 + e] : 0.f;  // x_prev @ w1_write
        p2[e] = Pt[48 + h * 4 + e];
    }
    ext6(p1, p2, L);
    const size_t base = (size_t)t * (NH * 6) + h * 6;
    jwo[base + 0] =  L[5]; jwo[base + 1] = -L[4]; jwo[base + 2] =  L[3];
    jwo[base + 3] =  L[2]; jwo[base + 4] = -L[1]; jwo[base + 5] =  L[0];
#pragma unroll
    for (int e = 0; e < 4; ++e) { p1[e] = Pt[96 + h * 4 + e]; p2[e] = Pt[144 + h * 4 + e]; }
    ext6(p1, p2, L);
#pragma unroll
    for (int i = 0; i < 6; ++i) rlo[base + i] = L[i];
    if (h == 0) {
        float acc = 0.f;
#pragma unroll
        for (int j = 0; j < NH; ++j) acc += 1.f / (1.f + expf(-(Pt[192 + j] + gb[j])));
        gateo[t] = acc * (1.f / 12.f);
    }
}

// ---------------- fused dual-path causal flash attention ----------------
// grid (32, 12): 64-query tile x head. 256 threads = 16x16, 4x4 per thread.
#define ALDS 68

#define SOFTMAX_UPDATE(Sv, Mv, Lv, Ov)                                             \
    {                                                                              \
        _Pragma("unroll")                                                          \
        for (int i = 0; i < 4; ++i) {                                              \
            float mx = fmaxf(fmaxf(Sv[i][0], Sv[i][1]), fmaxf(Sv[i][2], Sv[i][3]));\
            _Pragma("unroll")                                                      \
            for (int o = 8; o > 0; o >>= 1)                                        \
                mx = fmaxf(mx, __shfl_xor_sync(0xffffffffu, mx, o));               \
            const float mn = fmaxf(Mv[i], mx);                                     \
            const float corr = __expf(Mv[i] - mn);                                 \
            Mv[i] = mn;                                                            \
            float rsum = 0.f;                                                      \
            _Pragma("unroll")                                                      \
            for (int j = 0; j < 4; ++j) { Sv[i][j] = __expf(Sv[i][j] - mn); rsum += Sv[i][j]; } \
            _Pragma("unroll")                                                      \
            for (int o = 8; o > 0; o >>= 1)                                        \
                rsum += __shfl_xor_sync(0xffffffffu, rsum, o);                     \
            Lv[i] = Lv[i] * corr + rsum;                                           \
            _Pragma("unroll")                                                      \
            for (int j = 0; j < 4; ++j) Ov[i][j] *= corr;                          \
            *(float4*)&sP[(ty * 4 + i) * ALDS + tx * 4] =                          \
                make_float4(Sv[i][0], Sv[i][1], Sv[i][2], Sv[i][3]);               \
        }                                                                          \
    }

#define PV_ACC(Ov, SVt)                                                            \
    {                                                                              \
        _Pragma("unroll")                                                          \
        for (int s4 = 0; s4 < 16; ++s4) {                                          \
            float4 p[4], vv[4];                                                    \
            _Pragma("unroll")                                                      \
            for (int i = 0; i < 4; ++i) p[i] = *(const float4*)&sP[(ty * 4 + i) * ALDS + 4 * s4]; \
            _Pragma("unroll")                                                      \
            for (int j = 0; j < 4; ++j) vv[j] = *(const float4*)&SVt[(tx * 4 + j) * ALDS + 4 * s4]; \
            _Pragma("unroll")                                                      \
            for (int i = 0; i < 4; ++i) {                                          \
                _Pragma("unroll")                                                  \
                for (int j = 0; j < 4; ++j)                                        \
                    Ov[i][j] += p[i].x * vv[j].x + p[i].y * vv[j].y +              \
                                p[i].z * vv[j].z + p[i].w * vv[j].w;               \
            }                                                                      \
        }                                                                          \
    }

__global__ void attn_kernel(const float* __restrict__ qkv, const float* __restrict__ geov,
                            const float* __restrict__ rl, const float* __restrict__ jwg,
                            const float* __restrict__ gate, const float* __restrict__ inc,
                            float* __restrict__ comb)
{
    extern __shared__ float smem_f[];
    float* sQ   = smem_f;                  // 64*68
    float* sK   = sQ + 64 * ALDS;          // 64*68
    float* sVt  = sK + 64 * ALDS;          // 64*68 (transposed: [d][s])
    float* sGVt = sVt + 64 * ALDS;         // 64*68
    float* sP   = sGVt + 64 * ALDS;        // 64*68
    float* sRL  = sP + 64 * ALDS;          // 64*8
    float* sJWt = sRL + 64 * 8;            // 6*68 (transposed: [i][s])

    const int h = blockIdx.y;
    const int qb = gridDim.x - 1 - blockIdx.x;   // heavy tiles first
    const int qt0 = qb * 64;
    const int tid = threadIdx.x;
    const int tx = tid & 15, ty = tid >> 4;
    const int lr = tid >> 2;            // loader row 0..63
    const int ld0 = (tid & 3) * 16;     // 0,16,32,48

    { // load Q tile
        const float* src = qkv + (size_t)(qt0 + lr) * (3 * DD) + h * DHH + ld0;
#pragma unroll
        for (int u = 0; u < 4; ++u)
            *(float4*)&sQ[lr * ALDS + ld0 + 4 * u] = *(const float4*)(src + 4 * u);
    }
    if (tid < 64) {
#pragma unroll
        for (int i = 0; i < 6; ++i)
            sRL[tid * 8 + i] = rl[(size_t)(qt0 + tid) * (NH * 6) + h * 6 + i];
    }
    const float iscale = inc[h];

    float Os[4][4] = {}, Og[4][4] = {};
    float ms[4], ls[4], mg[4], lg[4];
#pragma unroll
    for (int i = 0; i < 4; ++i) { ms[i] = -1e30f; mg[i] = -1e30f; ls[i] = 0.f; lg[i] = 0.f; }

    for (int kt0 = 0; kt0 <= qt0; kt0 += 64) {
        __syncthreads();   // guard previous tile reads + Q/RL staging
        { // load K (natural), V/GV (transposed), JW (transposed)
            const float* ksrc = qkv  + (size_t)(kt0 + lr) * (3 * DD) +     DD + h * DHH + ld0;
            const float* vsrc = qkv  + (size_t)(kt0 + lr) * (3 * DD) + 2 * DD + h * DHH + ld0;
            const float* gsrc = geov + (size_t)(kt0 + lr) * DD + h * DHH + ld0;
#pragma unroll
            for (int u = 0; u < 4; ++u) {
                *(float4*)&sK[lr * ALDS + ld0 + 4 * u] = *(const float4*)(ksrc + 4 * u);
                const int dd = ld0 + 4 * u;
                float4 vv = *(const float4*)(vsrc + 4 * u);
                sVt[(dd + 0) * ALDS + lr] = vv.x; sVt[(dd + 1) * ALDS + lr] = vv.y;
                sVt[(dd + 2) * ALDS + lr] = vv.z; sVt[(dd + 3) * ALDS + lr] = vv.w;
                float4 gv = *(const float4*)(gsrc + 4 * u);
                sGVt[(dd + 0) * ALDS + lr] = gv.x; sGVt[(dd + 1) * ALDS + lr] = gv.y;
                sGVt[(dd + 2) * ALDS + lr] = gv.z; sGVt[(dd + 3) * ALDS + lr] = gv.w;
            }
        }
        if (tid < 64) {
#pragma unroll
            for (int i = 0; i < 6; ++i)
                sJWt[i * ALDS + tid] = jwg[(size_t)(kt0 + tid) * (NH * 6) + h * 6 + i];
        }
        __syncthreads();

        const bool diag = (kt0 == qt0);

        // ---- standard path logits: S = Q K^T * scale ----
        float s[4][4] = {};
#pragma unroll
        for (int d4 = 0; d4 < 16; ++d4) {
            float4 a[4], b[4];
#pragma unroll
            for (int i = 0; i < 4; ++i) a[i] = *(const float4*)&sQ[(ty * 4 + i) * ALDS + 4 * d4];
#pragma unroll
            for (int j = 0; j < 4; ++j) b[j] = *(const float4*)&sK[(tx * 4 + j) * ALDS + 4 * d4];
#pragma unroll
            for (int i = 0; i < 4; ++i)
#pragma unroll
                for (int j = 0; j < 4; ++j)
                    s[i][j] += a[i].x * b[j].x + a[i].y * b[j].y + a[i].z * b[j].z + a[i].w * b[j].w;
        }
#pragma unroll
        for (int i = 0; i < 4; ++i)
#pragma unroll
            for (int j = 0; j < 4; ++j) {
                s[i][j] *= 0.125f;
                if (diag && (tx * 4 + j > ty * 4 + i)) s[i][j] = -1e30f;
            }
        SOFTMAX_UPDATE(s, ms, ls, Os)
        __syncthreads();
        PV_ACC(Os, sVt)
        __syncthreads();

        // ---- geometric path logits: S = RL . JW * inc_scale ----
#pragma unroll
        for (int i = 0; i < 4; ++i)
#pragma unroll
            for (int j = 0; j < 4; ++j) s[i][j] = 0.f;
#pragma unroll
        for (int i6 = 0; i6 < 6; ++i6) {
            float ra[4];
#pragma unroll
            for (int i = 0; i < 4; ++i) ra[i] = sRL[(ty * 4 + i) * 8 + i6];
            const float4 jb = *(const float4*)&sJWt[i6 * ALDS + tx * 4];
#pragma unroll
            for (int i = 0; i < 4; ++i) {
                s[i][0] += ra[i] * jb.x; s[i][1] += ra[i] * jb.y;
                s[i][2] += ra[i] * jb.z; s[i][3] += ra[i] * jb.w;
            }
        }
#pragma unroll
        for (int i = 0; i < 4; ++i)
#pragma unroll
            for (int j = 0; j < 4; ++j) {
                s[i][j] *= iscale;
                if (diag && (tx * 4 + j > ty * 4 + i)) s[i][j] = -1e30f;
            }
        SOFTMAX_UPDATE(s, mg, lg, Og)
        __syncthreads();
        PV_ACC(Og, sGVt)
        // loop-top sync guards sP/sK/sVt reuse
    }

    // ---- finalize: combined = (1-g)*std + g*geo ----
#pragma unroll
    for (int i = 0; i < 4; ++i) {
        const int t = qt0 + ty * 4 + i;
        const float g = gate[t];
        const float is = (1.f - g) / ls[i];
        const float ig = g / lg[i];
        float4 o;
        o.x = Os[i][0] * is + Og[i][0] * ig;
        o.y = Os[i][1] * is + Og[i][1] * ig;
        o.z = Os[i][2] * is + Og[i][2] * ig;
        o.w = Os[i][3] * is + Og[i][3] * ig;
        *(float4*)&comb[(size_t)t * DD + h * DHH + tx * 4] = o;
    }
}

// ---------------- host ----------------
extern "C" void kernel_launch(void* const* d_in, const int* in_sizes, int n_in,
                              void* d_out, int out_size)
{
    (void)in_sizes; (void)n_in; (void)out_size;
    const float* x     = (const float*)d_in[0];
    const float* ln1g  = (const float*)d_in[1];
    const float* ln1b  = (const float*)d_in[2];
    const float* qkvw  = (const float*)d_in[3];
    const float* qkvb  = (const float*)d_in[4];
    const float* w1w   = (const float*)d_in[5];
    const float* w2w   = (const float*)d_in[6];
    const float* w1r   = (const float*)d_in[7];
    const float* w2r   = (const float*)d_in[8];
    const float* geovw = (const float*)d_in[9];
    const float* geovb = (const float*)d_in[10];
    const float* gatew = (const float*)d_in[11];
    const float* gateb = (const float*)d_in[12];
    const float* incs  = (const float*)d_in[13];
    const float* outw  = (const float*)d_in[14];
    const float* outb  = (const float*)d_in[15];
    const float* ln2g  = (const float*)d_in[16];
    const float* ln2b  = (const float*)d_in[17];
    const float* fcw   = (const float*)d_in[18];
    const float* fcb   = (const float*)d_in[19];
    const float* projw = (const float*)d_in[20];
    const float* projb = (const float*)d_in[21];
    float* out = (float*)d_out;

    float *xn, *qkv, *geov, *wcat, *Pp, *zb, *rlp, *jwp, *gatep, *combp, *hp, *mp, *actp;
    cudaGetSymbolAddress((void**)&xn,    g_xn);
    cudaGetSymbolAddress((void**)&qkv,   g_qkv);
    cudaGetSymbolAddress((void**)&geov,  g_geov);
    cudaGetSymbolAddress((void**)&wcat,  g_wcat);
    cudaGetSymbolAddress((void**)&Pp,    g_P);
    cudaGetSymbolAddress((void**)&zb,    g_zbias);
    cudaGetSymbolAddress((void**)&rlp,   g_rl);
    cudaGetSymbolAddress((void**)&jwp,   g_jw);
    cudaGetSymbolAddress((void**)&gatep, g_gate);
    cudaGetSymbolAddress((void**)&combp, g_comb);
    cudaGetSymbolAddress((void**)&hp,    g_h);
    cudaGetSymbolAddress((void**)&mp,    g_m);
    cudaGetSymbolAddress((void**)&actp,  g_act);

    const int smem_attn = (5 * 64 * ALDS + 64 * 8 + 6 * ALDS) * (int)sizeof(float);
    cudaFuncSetAttribute(attn_kernel, cudaFuncAttributeMaxDynamicSharedMemorySize, smem_attn);

    // 1. xn = LN1(x)
    ln_kernel<<<TT, 256>>>(x, ln1g, ln1b, xn);
    // 2. pack small-proj weights
    pack_w_kernel<<<(DD * 256 + 255) / 256, 256>>>(w1w, w2w, w1r, w2r, gatew, wcat);
    // 3. qkv = xn @ qkv_w + b
    gemm_tf32<false, false><<<dim3(18, 16), 256>>>(xn, qkvw, qkvb, nullptr, qkv, TT, 3 * DD, DD);
    // 4. geo_v = xn @ geo_v_w + b
    gemm_tf32<false, false><<<dim3(6, 16), 256>>>(xn, geovw, geovb, nullptr, geov, TT, DD, DD);
    // 5. P = xn @ Wcat (line projections + gate logits)
    gemm_tf32<false, false><<<dim3(2, 16), 256>>>(xn, wcat, zb, nullptr, Pp, TT, 256, DD);
    // 6. exterior lines + J + gate
    lines_kernel<<<(TT * NH + 255) / 256, 256>>>(Pp, gateb, rlp, jwp, gatep);
    // 7. fused dual-path attention -> combined
    attn_kernel<<<dim3(32, NH), 256, smem_attn>>>(qkv, geov, rlp, jwp, gatep, incs, combp);
    // 8. h = x + combined @ out_w + b
    gemm_tf32<false, true><<<dim3(6, 16), 256>>>(combp, outw, outb, x, hp, TT, DD, DD);
    // 9. m = LN2(h)
    ln_kernel<<<TT, 256>>>(hp, ln2g, ln2b, mp);
    // 10. act = gelu(m @ fc_w + b)
    gemm_tf32<true, false><<<dim3(24, 16), 256>>>(mp, fcw, fcb, nullptr, actp, TT, 4 * DD, DD);
    // 11. out = h + act @ proj_w + b
    gemm_tf32<false, true><<<dim3(6, 16), 256>>>(actp, projw, projb, hp, out, TT, DD, 4 * DD);
}

// round 5
// speedup vs baseline: 2.1465x; 1.8173x over previous
#include <cuda_runtime.h>
#include <math.h>
#include <stdint.h>

#define TT 2048
#define DD 768
#define NH 12
#define DHH 64
#define FD 3328            // fused GEMM width: 2304 qkv + 768 geov + 256 smallproj

// ---------------- scratch (device globals, no allocation) ----------------
__device__ float g_xn[TT * DD];            // ln1(x)
__device__ float g_fused[TT * FD];         // [qkv | geov | P]
__device__ float g_wpack[DD * FD];         // packed weights
__device__ float g_bpack[FD];              // packed bias
__device__ float g_rl[TT * NH * 6];        // read lines (normalized)
__device__ float g_jw[TT * NH * 6];        // J @ write lines
__device__ float g_gate[TT];               // gate scalar per token
__device__ float g_comb[TT * DD];          // combined attention output
__device__ float g_h[TT * DD];             // h = x + attn
__device__ float g_m[TT * DD];             // ln2(h)
__device__ float g_act[TT * 4 * DD];       // gelu(fc)

// ---------------- helpers ----------------
__device__ __forceinline__ uint32_t f2tf32(float x)
{
    uint32_t r;
    asm("cvt.rna.tf32.f32 %0, %1;" : "=r"(r) : "f"(x));
    return r;
}

__device__ __forceinline__ float gelu_f(float x)
{
    const float x3 = x * x * x;
    return 0.5f * x * (1.f + tanhf(0.7978845608028654f * (x + 0.044715f * x3)));
}

__device__ __forceinline__ void mma_tf32(float* d, const uint32_t* a, const uint32_t* b)
{
    asm volatile("mma.sync.aligned.m16n8k8.row.col.f32.tf32.tf32.f32 "
                 "{%0,%1,%2,%3}, {%4,%5,%6,%7}, {%8,%9}, {%0,%1,%2,%3};"
                 : "+f"(d[0]), "+f"(d[1]), "+f"(d[2]), "+f"(d[3])
                 : "r"(a[0]), "r"(a[1]), "r"(a[2]), "r"(a[3]), "r"(b[0]), "r"(b[1]));
}

// ---------------- LayerNorm ----------------
__global__ void ln_kernel(const float* __restrict__ x, const float* __restrict__ g,
                          const float* __restrict__ b, float* __restrict__ y)
{
    const int t = blockIdx.x, tid = threadIdx.x;
    const float* xr = x + (size_t)t * DD;
    float v[3];
    float s = 0.f, s2 = 0.f;
#pragma unroll
    for (int i = 0; i < 3; ++i) {
        v[i] = xr[tid + i * 256];
        s += v[i];
        s2 += v[i] * v[i];
    }
    __shared__ float rs[8], rs2[8];
#pragma unroll
    for (int o = 16; o > 0; o >>= 1) {
        s  += __shfl_xor_sync(0xffffffffu, s, o);
        s2 += __shfl_xor_sync(0xffffffffu, s2, o);
    }
    const int w = tid >> 5, l = tid & 31;
    if (l == 0) { rs[w] = s; rs2[w] = s2; }
    __syncthreads();
    s = 0.f; s2 = 0.f;
#pragma unroll
    for (int i = 0; i < 8; ++i) { s += rs[i]; s2 += rs2[i]; }
    const float mean = s * (1.f / 768.f);
    const float var  = s2 * (1.f / 768.f) - mean * mean;
    const float rstd = rsqrtf(var + 1e-5f);
#pragma unroll
    for (int i = 0; i < 3; ++i) {
        const int c = tid + i * 256;
        y[(size_t)t * DD + c] = (v[i] - mean) * rstd * g[c] + b[c];
    }
}

// ---------------- tf32 tensor-core GEMM: 128x128x16, 256 thr, 8 warps ----------------
#define SPAD 136

#define LOAD_TILE(ktof, buf)                                                   \
    {                                                                          \
        _Pragma("unroll")                                                      \
        for (int hh = 0; hh < 2; ++hh) {                                       \
            float4 v = *(const float4*)(Aglob + (ktof) + hh * 8);              \
            const int kc = acol4 * 4 + hh * 8;                                 \
            As[buf][(kc + 0) * SPAD + arow] = f2tf32(v.x);                     \
            As[buf][(kc + 1) * SPAD + arow] = f2tf32(v.y);                     \
            As[buf][(kc + 2) * SPAD + arow] = f2tf32(v.z);                     \
            As[buf][(kc + 3) * SPAD + arow] = f2tf32(v.w);                     \
        }                                                                      \
        _Pragma("unroll")                                                      \
        for (int hh = 0; hh < 2; ++hh) {                                       \
            float4 v = *(const float4*)(Bglob + (size_t)(ktof) * N + hh * 64); \
            const int nc = bn4 * 4 + hh * 64;                                  \
            Bs[buf][bk * SPAD + nc + 0] = f2tf32(v.x);                         \
            Bs[buf][bk * SPAD + nc + 1] = f2tf32(v.y);                         \
            Bs[buf][bk * SPAD + nc + 2] = f2tf32(v.z);                         \
            Bs[buf][bk * SPAD + nc + 3] = f2tf32(v.w);                         \
        }                                                                      \
    }

#define COMPUTE_TILE(buf)                                                      \
    {                                                                          \
        _Pragma("unroll")                                                      \
        for (int ks = 0; ks < 2; ++ks) {                                       \
            const int kb = ks * 8 + (lane & 3);                                \
            uint32_t a[2][4], b[8][2];                                         \
            _Pragma("unroll")                                                  \
            for (int mi = 0; mi < 2; ++mi) {                                   \
                const int r = warpM + mi * 16 + (lane >> 2);                   \
                a[mi][0] = As[buf][kb * SPAD + r];                             \
                a[mi][1] = As[buf][kb * SPAD + r + 8];                         \
                a[mi][2] = As[buf][(kb + 4) * SPAD + r];                       \
                a[mi][3] = As[buf][(kb + 4) * SPAD + r + 8];                   \
            }                                                                  \
            _Pragma("unroll")                                                  \
            for (int ni = 0; ni < 8; ++ni) {                                   \
                const int c = warpN + ni * 8 + (lane >> 2);                    \
                b[ni][0] = Bs[buf][kb * SPAD + c];                             \
                b[ni][1] = Bs[buf][(kb + 4) * SPAD + c];                       \
            }                                                                  \
            _Pragma("unroll")                                                  \
            for (int mi = 0; mi < 2; ++mi)                                     \
                _Pragma("unroll")                                              \
                for (int ni = 0; ni < 8; ++ni)                                 \
                    mma_tf32(acc[mi][ni], a[mi], b[ni]);                       \
        }                                                                      \
    }

template <bool GELU, bool RES>
__global__ __launch_bounds__(256) void gemm_tf32(const float* __restrict__ A,
                                                 const float* __restrict__ B,
                                                 const float* __restrict__ bias,
                                                 const float* __restrict__ R,
                                                 float* __restrict__ C,
                                                 int M, int N, int K)
{
    __shared__ uint32_t As[2][16 * SPAD];
    __shared__ uint32_t Bs[2][16 * SPAD];
    const int tid = threadIdx.x, lane = tid & 31, w = tid >> 5;
    const int warpM = (w & 3) * 32, warpN = (w >> 2) * 64;
    const int m0 = blockIdx.y * 128, n0 = blockIdx.x * 128;
    const int arow = tid & 127, acol4 = tid >> 7;
    const int bk = tid >> 4,   bn4 = tid & 15;
    const float* Aglob = A + (size_t)(m0 + arow) * K + acol4 * 4;
    const float* Bglob = B + (size_t)bk * N + n0 + bn4 * 4;

    float acc[2][8][4] = {};

    LOAD_TILE(0, 0);
    __syncthreads();
    const int ntiles = K >> 4;
    for (int kt = 0; kt < ntiles; ++kt) {
        const int buf = kt & 1;
        if (kt + 1 < ntiles) LOAD_TILE((kt + 1) * 16, buf ^ 1);
        COMPUTE_TILE(buf);
        __syncthreads();
    }

#pragma unroll
    for (int mi = 0; mi < 2; ++mi) {
#pragma unroll
        for (int ni = 0; ni < 8; ++ni) {
            const int col = n0 + warpN + ni * 8 + 2 * (lane & 3);
            const float b0 = bias[col], b1 = bias[col + 1];
#pragma unroll
            for (int r = 0; r < 2; ++r) {
                const int row = m0 + warpM + mi * 16 + (lane >> 2) + 8 * r;
                float o0 = acc[mi][ni][2 * r + 0] + b0;
                float o1 = acc[mi][ni][2 * r + 1] + b1;
                if (GELU) { o0 = gelu_f(o0); o1 = gelu_f(o1); }
                if (RES) {
                    o0 += R[(size_t)row * N + col];
                    o1 += R[(size_t)row * N + col + 1];
                }
                *(float2*)&C[(size_t)row * N + col] = make_float2(o0, o1);
            }
        }
    }
}

// ---------------- pack fused weights [768, 3328] + bias ----------------
__global__ void pack_kernel(const float* __restrict__ qkvw, const float* __restrict__ geovw,
                            const float* __restrict__ w1w, const float* __restrict__ w2w,
                            const float* __restrict__ w1r, const float* __restrict__ w2r,
                            const float* __restrict__ gw,
                            const float* __restrict__ qkvb, const float* __restrict__ geovb,
                            float* __restrict__ Wout, float* __restrict__ bout)
{
    const int idx = blockIdx.x * 256 + threadIdx.x;
    if (idx >= DD * FD) return;
    const int k = idx / FD, c = idx % FD;
    float v = 0.f;
    if (c < 2304) v = qkvw[(size_t)k * 2304 + c];
    else if (c < 3072) v = geovw[(size_t)k * 768 + (c - 2304)];
    else {
        const int c2 = c - 3072;
        if (c2 < 48)       v = w1w[k * 48 + c2];
        else if (c2 < 96)  v = w2w[k * 48 + c2 - 48];
        else if (c2 < 144) v = w1r[k * 48 + c2 - 96];
        else if (c2 < 192) v = w2r[k * 48 + c2 - 144];
        else if (c2 < 204) v = gw[k * 12 + c2 - 192];
    }
    Wout[idx] = v;
    if (k == 0)
        bout[c] = (c < 2304) ? qkvb[c] : ((c < 3072) ? geovb[c - 2304] : 0.f);
}

// ---------------- exterior lines + J map + gate ----------------
__device__ __forceinline__ void ext6(const float* p, const float* q, float* L)
{
    L[0] = p[0] * q[1] - p[1] * q[0];
    L[1] = p[0] * q[2] - p[2] * q[0];
    L[2] = p[0] * q[3] - p[3] * q[0];
    L[3] = p[1] * q[2] - p[2] * q[1];
    L[4] = p[1] * q[3] - p[3] * q[1];
    L[5] = p[2] * q[3] - p[3] * q[2];
    float n2 = 0.f;
#pragma unroll
    for (int i = 0; i < 6; ++i) n2 += L[i] * L[i];
    const float inv = 1.f / fmaxf(sqrtf(n2), 1e-12f);
#pragma unroll
    for (int i = 0; i < 6; ++i) L[i] *= inv;
}

__global__ void lines_kernel(const float* __restrict__ fused, const float* __restrict__ gb,
                             float* __restrict__ rlo, float* __restrict__ jwo,
                             float* __restrict__ gateo)
{
    const int idx = blockIdx.x * 256 + threadIdx.x;
    if (idx >= TT * NH) return;
    const int t = idx / NH, h = idx % NH;
    const float* Pt = fused + (size_t)t * FD + 3072;
    float p1[4], p2[4], L[6];
#pragma unroll
    for (int e = 0; e < 4; ++e) {
        p1[e] = (t > 0) ? fused[(size_t)(t - 1) * FD + 3072 + h * 4 + e] : 0.f;
        p2[e] = Pt[48 + h * 4 + e];
    }
    ext6(p1, p2, L);
    const size_t base = (size_t)t * (NH * 6) + h * 6;
    jwo[base + 0] =  L[5]; jwo[base + 1] = -L[4]; jwo[base + 2] =  L[3];
    jwo[base + 3] =  L[2]; jwo[base + 4] = -L[1]; jwo[base + 5] =  L[0];
#pragma unroll
    for (int e = 0; e < 4; ++e) { p1[e] = Pt[96 + h * 4 + e]; p2[e] = Pt[144 + h * 4 + e]; }
    ext6(p1, p2, L);
#pragma unroll
    for (int i = 0; i < 6; ++i) rlo[base + i] = L[i];
    if (h == 0) {
        float acc = 0.f;
#pragma unroll
        for (int j = 0; j < NH; ++j) acc += 1.f / (1.f + expf(-(Pt[192 + j] + gb[j])));
        gateo[t] = acc * (1.f / 12.f);
    }
}

// ---------------- fused dual-path causal flash attention (tf32 mma) ----------------
// grid (32, 12), 128 threads = 4 warps; each warp: m16 x n64 via m16n8k8.
#define AST 76

__device__ __forceinline__ void softmax_update_mma(float S[8][4], float* m, float* l,
                                                   float O[8][4], uint32_t* sP,
                                                   int warpM, int g, int t)
{
    float mx0 = -1e30f, mx1 = -1e30f;
#pragma unroll
    for (int ni = 0; ni < 8; ++ni) {
        mx0 = fmaxf(mx0, fmaxf(S[ni][0], S[ni][1]));
        mx1 = fmaxf(mx1, fmaxf(S[ni][2], S[ni][3]));
    }
#pragma unroll
    for (int o = 1; o <= 2; o <<= 1) {
        mx0 = fmaxf(mx0, __shfl_xor_sync(0xffffffffu, mx0, o));
        mx1 = fmaxf(mx1, __shfl_xor_sync(0xffffffffu, mx1, o));
    }
    const float mn0 = fmaxf(m[0], mx0), mn1 = fmaxf(m[1], mx1);
    const float c0 = __expf(m[0] - mn0), c1 = __expf(m[1] - mn1);
    m[0] = mn0; m[1] = mn1;
    float s0 = 0.f, s1 = 0.f;
#pragma unroll
    for (int ni = 0; ni < 8; ++ni) {
        const float p0 = __expf(S[ni][0] - mn0), p1 = __expf(S[ni][1] - mn0);
        const float p2 = __expf(S[ni][2] - mn1), p3 = __expf(S[ni][3] - mn1);
        s0 += p0 + p1; s1 += p2 + p3;
        const int sc = ni * 8 + 2 * t;
        sP[(sc    ) * AST + warpM + g    ] = f2tf32(p0);
        sP[(sc + 1) * AST + warpM + g    ] = f2tf32(p1);
        sP[(sc    ) * AST + warpM + g + 8] = f2tf32(p2);
        sP[(sc + 1) * AST + warpM + g + 8] = f2tf32(p3);
        O[ni][0] *= c0; O[ni][1] *= c0; O[ni][2] *= c1; O[ni][3] *= c1;
    }
#pragma unroll
    for (int o = 1; o <= 2; o <<= 1) {
        s0 += __shfl_xor_sync(0xffffffffu, s0, o);
        s1 += __shfl_xor_sync(0xffffffffu, s1, o);
    }
    l[0] = l[0] * c0 + s0;
    l[1] = l[1] * c1 + s1;
}

__global__ __launch_bounds__(128) void attn_kernel(const float* __restrict__ fused,
                                                   const float* __restrict__ rl,
                                                   const float* __restrict__ jwg,
                                                   const float* __restrict__ gate,
                                                   const float* __restrict__ inc,
                                                   float* __restrict__ comb)
{
    extern __shared__ uint32_t sm[];
    uint32_t* sQ  = sm;              // [d][q] 64xAST
    uint32_t* sK  = sQ  + 64 * AST;  // [d][s]
    uint32_t* sV  = sK  + 64 * AST;  // [s][d]
    uint32_t* sGV = sV  + 64 * AST;  // [s][d]
    uint32_t* sP  = sGV + 64 * AST;  // [s][q]
    uint32_t* sRL = sP  + 64 * AST;  // [i][q] 8xAST (rows 6,7 zero)
    uint32_t* sJW = sRL + 8 * AST;   // [i][s] 8xAST (rows 6,7 zero)

    const int h = blockIdx.y;
    const int qb = gridDim.x - 1 - blockIdx.x;  // heavy tiles first
    const int qt0 = qb * 64;
    const int tid = threadIdx.x;
    const int lane = tid & 31, w = tid >> 5;
    const int g = lane >> 2, t = lane & 3;
    const int warpM = w * 16;
    const int lr = tid >> 1, d0 = (tid & 1) * 32;

    if (tid < 2 * AST) { sRL[6 * AST + tid] = 0; sJW[6 * AST + tid] = 0; }
    { // load Q transposed
        const float* src = fused + (size_t)(qt0 + lr) * FD + h * DHH + d0;
#pragma unroll
        for (int u = 0; u < 8; ++u) {
            float4 v = *(const float4*)(src + 4 * u);
            const int d = d0 + 4 * u;
            sQ[(d + 0) * AST + lr] = f2tf32(v.x);
            sQ[(d + 1) * AST + lr] = f2tf32(v.y);
            sQ[(d + 2) * AST + lr] = f2tf32(v.z);
            sQ[(d + 3) * AST + lr] = f2tf32(v.w);
        }
    }
    if (tid < 64) {
#pragma unroll
        for (int i = 0; i < 6; ++i)
            sRL[i * AST + tid] = f2tf32(rl[(size_t)(qt0 + tid) * (NH * 6) + h * 6 + i]);
    }
    const float iscale = inc[h];

    float Os[8][4] = {}, Og[8][4] = {};
    float ms[2] = {-1e30f, -1e30f}, mg[2] = {-1e30f, -1e30f}, ls[2] = {}, lg[2] = {};

    for (int kt0 = 0; kt0 <= qt0; kt0 += 64) {
        __syncthreads();
        { // load K transposed, V/GV natural, JW
            const float* ksrc = fused + (size_t)(kt0 + lr) * FD +  DD + h * DHH + d0;
            const float* vsrc = fused + (size_t)(kt0 + lr) * FD + 2 * DD + h * DHH + d0;
            const float* gsrc = fused + (size_t)(kt0 + lr) * FD + 3 * DD + h * DHH + d0;
#pragma unroll
            for (int u = 0; u < 8; ++u) {
                const int d = d0 + 4 * u;
                float4 kv = *(const float4*)(ksrc + 4 * u);
                sK[(d + 0) * AST + lr] = f2tf32(kv.x);
                sK[(d + 1) * AST + lr] = f2tf32(kv.y);
                sK[(d + 2) * AST + lr] = f2tf32(kv.z);
                sK[(d + 3) * AST + lr] = f2tf32(kv.w);
                float4 vv = *(const float4*)(vsrc + 4 * u);
                uint4 pv; pv.x = f2tf32(vv.x); pv.y = f2tf32(vv.y);
                pv.z = f2tf32(vv.z); pv.w = f2tf32(vv.w);
                *(uint4*)&sV[lr * AST + d] = pv;
                float4 gv = *(const float4*)(gsrc + 4 * u);
                uint4 pg; pg.x = f2tf32(gv.x); pg.y = f2tf32(gv.y);
                pg.z = f2tf32(gv.z); pg.w = f2tf32(gv.w);
                *(uint4*)&sGV[lr * AST + d] = pg;
            }
        }
        if (tid < 64) {
#pragma unroll
            for (int i = 0; i < 6; ++i)
                sJW[i * AST + tid] = f2tf32(jwg[(size_t)(kt0 + tid) * (NH * 6) + h * 6 + i]);
        }
        __syncthreads();
        const bool diag = (kt0 == qt0);

        // ==== std path: S = Q K^T * 1/8 ====
        float S[8][4] = {};
#pragma unroll
        for (int k8 = 0; k8 < 8; ++k8) {
            const int kk = k8 * 8 + t;
            uint32_t a[4], b[2];
            a[0] = sQ[kk * AST + warpM + g];
            a[1] = sQ[kk * AST + warpM + g + 8];
            a[2] = sQ[(kk + 4) * AST + warpM + g];
            a[3] = sQ[(kk + 4) * AST + warpM + g + 8];
#pragma unroll
            for (int ni = 0; ni < 8; ++ni) {
                b[0] = sK[kk * AST + ni * 8 + g];
                b[1] = sK[(kk + 4) * AST + ni * 8 + g];
                mma_tf32(S[ni], a, b);
            }
        }
#pragma unroll
        for (int ni = 0; ni < 8; ++ni) {
            const int sc = ni * 8 + 2 * t;
#pragma unroll
            for (int j = 0; j < 4; ++j) S[ni][j] *= 0.125f;
            if (diag) {
                const int r0 = warpM + g, r1 = r0 + 8;
                if (sc     > r0) S[ni][0] = -1e30f;
                if (sc + 1 > r0) S[ni][1] = -1e30f;
                if (sc     > r1) S[ni][2] = -1e30f;
                if (sc + 1 > r1) S[ni][3] = -1e30f;
            }
        }
        softmax_update_mma(S, ms, ls, Os, sP, warpM, g, t);
        __syncwarp();
#pragma unroll
        for (int k8 = 0; k8 < 8; ++k8) {
            const int kk = k8 * 8 + t;
            uint32_t a[4], b[2];
            a[0] = sP[kk * AST + warpM + g];
            a[1] = sP[kk * AST + warpM + g + 8];
            a[2] = sP[(kk + 4) * AST + warpM + g];
            a[3] = sP[(kk + 4) * AST + warpM + g + 8];
#pragma unroll
            for (int ni = 0; ni < 8; ++ni) {
                b[0] = sV[kk * AST + ni * 8 + g];
                b[1] = sV[(kk + 4) * AST + ni * 8 + g];
                mma_tf32(Os[ni], a, b);
            }
        }
        __syncwarp();

        // ==== geo path: S = RL . JW * inc_scale (k=8, padded) ====
#pragma unroll
        for (int ni = 0; ni < 8; ++ni)
#pragma unroll
            for (int j = 0; j < 4; ++j) S[ni][j] = 0.f;
        {
            uint32_t a[4], b[2];
            a[0] = sRL[t * AST + warpM + g];
            a[1] = sRL[t * AST + warpM + g + 8];
            a[2] = sRL[(t + 4) * AST + warpM + g];
            a[3] = sRL[(t + 4) * AST + warpM + g + 8];
#pragma unroll
            for (int ni = 0; ni < 8; ++ni) {
                b[0] = sJW[t * AST + ni * 8 + g];
                b[1] = sJW[(t + 4) * AST + ni * 8 + g];
                mma_tf32(S[ni], a, b);
            }
        }
#pragma unroll
        for (int ni = 0; ni < 8; ++ni) {
            const int sc = ni * 8 + 2 * t;
#pragma unroll
            for (int j = 0; j < 4; ++j) S[ni][j] *= iscale;
            if (diag) {
                const int r0 = warpM + g, r1 = r0 + 8;
                if (sc     > r0) S[ni][0] = -1e30f;
                if (sc + 1 > r0) S[ni][1] = -1e30f;
                if (sc     > r1) S[ni][2] = -1e30f;
                if (sc + 1 > r1) S[ni][3] = -1e30f;
            }
        }
        softmax_update_mma(S, mg, lg, Og, sP, warpM, g, t);
        __syncwarp();
#pragma unroll
        for (int k8 = 0; k8 < 8; ++k8) {
            const int kk = k8 * 8 + t;
            uint32_t a[4], b[2];
            a[0] = sP[kk * AST + warpM + g];
            a[1] = sP[kk * AST + warpM + g + 8];
            a[2] = sP[(kk + 4) * AST + warpM + g];
            a[3] = sP[(kk + 4) * AST + warpM + g + 8];
#pragma unroll
            for (int ni = 0; ni < 8; ++ni) {
                b[0] = sGV[kk * AST + ni * 8 + g];
                b[1] = sGV[(kk + 4) * AST + ni * 8 + g];
                mma_tf32(Og[ni], a, b);
            }
        }
        __syncwarp();
    }

    // ---- finalize: combined = (1-g)*std/ls + g*geo/lg ----
    const int r0 = qt0 + warpM + g, r1 = r0 + 8;
    const float g0 = gate[r0], g1 = gate[r1];
    const float as0 = (1.f - g0) / ls[0], ag0 = g0 / lg[0];
    const float as1 = (1.f - g1) / ls[1], ag1 = g1 / lg[1];
#pragma unroll
    for (int ni = 0; ni < 8; ++ni) {
        const int d = ni * 8 + 2 * t;
        float2 o0 = make_float2(Os[ni][0] * as0 + Og[ni][0] * ag0,
                                Os[ni][1] * as0 + Og[ni][1] * ag0);
        float2 o1 = make_float2(Os[ni][2] * as1 + Og[ni][2] * ag1,
                                Os[ni][3] * as1 + Og[ni][3] * ag1);
        *(float2*)&comb[(size_t)r0 * DD + h * DHH + d] = o0;
        *(float2*)&comb[(size_t)r1 * DD + h * DHH + d] = o1;
    }
}

// ---------------- host ----------------
extern "C" void kernel_launch(void* const* d_in, const int* in_sizes, int n_in,
                              void* d_out, int out_size)
{
    (void)in_sizes; (void)n_in; (void)out_size;
    const float* x     = (const float*)d_in[0];
    const float* ln1g  = (const float*)d_in[1];
    const float* ln1b  = (const float*)d_in[2];
    const float* qkvw  = (const float*)d_in[3];
    const float* qkvb  = (const float*)d_in[4];
    const float* w1w   = (const float*)d_in[5];
    const float* w2w   = (const float*)d_in[6];
    const float* w1r   = (const float*)d_in[7];
    const float* w2r   = (const float*)d_in[8];
    const float* geovw = (const float*)d_in[9];
    const float* geovb = (const float*)d_in[10];
    const float* gatew = (const float*)d_in[11];
    const float* gateb = (const float*)d_in[12];
    const float* incs  = (const float*)d_in[13];
    const float* outw  = (const float*)d_in[14];
    const float* outb  = (const float*)d_in[15];
    const float* ln2g  = (const float*)d_in[16];
    const float* ln2b  = (const float*)d_in[17];
    const float* fcw   = (const float*)d_in[18];
    const float* fcb   = (const float*)d_in[19];
    const float* projw = (const float*)d_in[20];
    const float* projb = (const float*)d_in[21];
    float* out = (float*)d_out;

    float *xn, *fz, *wp, *bp, *rlp, *jwp, *gatep, *combp, *hp, *mp, *actp;
    cudaGetSymbolAddress((void**)&xn,    g_xn);
    cudaGetSymbolAddress((void**)&fz,    g_fused);
    cudaGetSymbolAddress((void**)&wp,    g_wpack);
    cudaGetSymbolAddress((void**)&bp,    g_bpack);
    cudaGetSymbolAddress((void**)&rlp,   g_rl);
    cudaGetSymbolAddress((void**)&jwp,   g_jw);
    cudaGetSymbolAddress((void**)&gatep, g_gate);
    cudaGetSymbolAddress((void**)&combp, g_comb);
    cudaGetSymbolAddress((void**)&hp,    g_h);
    cudaGetSymbolAddress((void**)&mp,    g_m);
    cudaGetSymbolAddress((void**)&actp,  g_act);

    const int smem_attn = (5 * 64 * AST + 2 * 8 * AST) * (int)sizeof(uint32_t);
    cudaFuncSetAttribute(attn_kernel, cudaFuncAttributeMaxDynamicSharedMemorySize, smem_attn);

    // 1. xn = LN1(x)
    ln_kernel<<<TT, 256>>>(x, ln1g, ln1b, xn);
    // 2. pack fused weights + bias
    pack_kernel<<<(DD * FD + 255) / 256, 256>>>(qkvw, geovw, w1w, w2w, w1r, w2r, gatew,
                                                qkvb, geovb, wp, bp);
    // 3. fused = xn @ [qkv_w | geov_w | wcat] + bias   (2048 x 3328 x 768)
    gemm_tf32<false, false><<<dim3(26, 16), 256>>>(xn, wp, bp, nullptr, fz, TT, FD, DD);
    // 4. exterior lines + J + gate
    lines_kernel<<<(TT * NH + 255) / 256, 256>>>(fz, gateb, rlp, jwp, gatep);
    // 5. fused dual-path attention -> combined
    attn_kernel<<<dim3(32, NH), 128, smem_attn>>>(fz, rlp, jwp, gatep, incs, combp);
    // 6. h = x + combined @ out_w + b
    gemm_tf32<false, true><<<dim3(6, 16), 256>>>(combp, outw, outb, x, hp, TT, DD, DD);
    // 7. m = LN2(h)
    ln_kernel<<<TT, 256>>>(hp, ln2g, ln2b, mp);
    // 8. act = gelu(m @ fc_w + b)
    gemm_tf32<true, false><<<dim3(24, 16), 256>>>(mp, fcw, fcb, nullptr, actp, TT, 4 * DD, DD);
    // 9. out = h + act @ proj_w + b
    gemm_tf32<false, true><<<dim3(6, 16), 256>>>(actp, projw, projb, hp, out, TT, DD, 4 * DD);
}

// round 8
// speedup vs baseline: 2.4929x; 1.1614x over previous
#include <cuda_runtime.h>
#include <math.h>
#include <stdint.h>

#define TT 2048
#define DD 768
#define NH 12
#define DHH 64
#define FD 3328            // fused GEMM width: 2304 qkv + 768 geov + 256 smallproj

// ---------------- scratch (device globals, no allocation) ----------------
__device__ float g_xn[TT * DD];            // ln1(x)
__device__ float g_fused[TT * FD];         // [qkv | geov | P]
__device__ float g_wpack[DD * FD];         // packed weights
__device__ float g_bpack[FD];              // packed bias
__device__ float g_rl[TT * NH * 6];        // read lines (normalized)
__device__ float g_jw[TT * NH * 6];        // J @ write lines
__device__ float g_gate[TT];               // gate scalar per token
__device__ float g_comb[TT * DD];          // combined attention output
__device__ float g_h[TT * DD];             // h = x + attn
__device__ float g_m[TT * DD];             // ln2(h)
__device__ float g_act[TT * 4 * DD];       // gelu(fc)
__device__ float g_part[4 * TT * DD];      // split-K partials

// ---------------- helpers ----------------
__device__ __forceinline__ uint32_t f2tf32(float x)
{
    uint32_t r;
    asm("cvt.rna.tf32.f32 %0, %1;" : "=r"(r) : "f"(x));
    return r;
}

__device__ __forceinline__ float gelu_f(float x)
{
    const float x3 = x * x * x;
    return 0.5f * x * (1.f + tanhf(0.7978845608028654f * (x + 0.044715f * x3)));
}

__device__ __forceinline__ void mma_tf32(float* d, const uint32_t* a, const uint32_t* b)
{
    asm volatile("mma.sync.aligned.m16n8k8.row.col.f32.tf32.tf32.f32 "
                 "{%0,%1,%2,%3}, {%4,%5,%6,%7}, {%8,%9}, {%0,%1,%2,%3};"
                 : "+f"(d[0]), "+f"(d[1]), "+f"(d[2]), "+f"(d[3])
                 : "r"(a[0]), "r"(a[1]), "r"(a[2]), "r"(a[3]), "r"(b[0]), "r"(b[1]));
}

// ---------------- LayerNorm ----------------
__global__ void ln_kernel(const float* __restrict__ x, const float* __restrict__ g,
                          const float* __restrict__ b, float* __restrict__ y)
{
    const int t = blockIdx.x, tid = threadIdx.x;
    const float* xr = x + (size_t)t * DD;
    float v[3];
    float s = 0.f, s2 = 0.f;
#pragma unroll
    for (int i = 0; i < 3; ++i) {
        v[i] = xr[tid + i * 256];
        s += v[i];
        s2 += v[i] * v[i];
    }
    __shared__ float rs[8], rs2[8];
#pragma unroll
    for (int o = 16; o > 0; o >>= 1) {
        s  += __shfl_xor_sync(0xffffffffu, s, o);
        s2 += __shfl_xor_sync(0xffffffffu, s2, o);
    }
    const int w = tid >> 5, l = tid & 31;
    if (l == 0) { rs[w] = s; rs2[w] = s2; }
    __syncthreads();
    s = 0.f; s2 = 0.f;
#pragma unroll
    for (int i = 0; i < 8; ++i) { s += rs[i]; s2 += rs2[i]; }
    const float mean = s * (1.f / 768.f);
    const float var  = s2 * (1.f / 768.f) - mean * mean;
    const float rstd = rsqrtf(var + 1e-5f);
#pragma unroll
    for (int i = 0; i < 3; ++i) {
        const int c = tid + i * 256;
        y[(size_t)t * DD + c] = (v[i] - mean) * rstd * g[c] + b[c];
    }
}

// ---------------- tf32 tensor-core GEMM: 128x128x16, 256 thr, 8 warps ----------------
#define SPAD 136

#define LOAD_TILE(ktof, buf)                                                   \
    {                                                                          \
        _Pragma("unroll")                                                      \
        for (int hh = 0; hh < 2; ++hh) {                                       \
            float4 v = *(const float4*)(Aglob + (ktof) + hh * 8);              \
            const int kc = acol4 * 4 + hh * 8;                                 \
            As[buf][(kc + 0) * SPAD + arow] = f2tf32(v.x);                     \
            As[buf][(kc + 1) * SPAD + arow] = f2tf32(v.y);                     \
            As[buf][(kc + 2) * SPAD + arow] = f2tf32(v.z);                     \
            As[buf][(kc + 3) * SPAD + arow] = f2tf32(v.w);                     \
        }                                                                      \
        _Pragma("unroll")                                                      \
        for (int hh = 0; hh < 2; ++hh) {                                       \
            float4 v = *(const float4*)(Bglob + (size_t)(ktof) * N + hh * 64); \
            const int nc = bn4 * 4 + hh * 64;                                  \
            Bs[buf][bk * SPAD + nc + 0] = f2tf32(v.x);                         \
            Bs[buf][bk * SPAD + nc + 1] = f2tf32(v.y);                         \
            Bs[buf][bk * SPAD + nc + 2] = f2tf32(v.z);                         \
            Bs[buf][bk * SPAD + nc + 3] = f2tf32(v.w);                         \
        }                                                                      \
    }

#define COMPUTE_TILE(buf)                                                      \
    {                                                                          \
        _Pragma("unroll")                                                      \
        for (int ks = 0; ks < 2; ++ks) {                                       \
            const int kb = ks * 8 + (lane & 3);                                \
            uint32_t a[2][4], b[8][2];                                         \
            _Pragma("unroll")                                                  \
            for (int mi = 0; mi < 2; ++mi) {                                   \
                const int r = warpM + mi * 16 + (lane >> 2);                   \
                a[mi][0] = As[buf][kb * SPAD + r];                             \
                a[mi][1] = As[buf][kb * SPAD + r + 8];                         \
                a[mi][2] = As[buf][(kb + 4) * SPAD + r];                       \
                a[mi][3] = As[buf][(kb + 4) * SPAD + r + 8];                   \
            }                                                                  \
            _Pragma("unroll")                                                  \
            for (int ni = 0; ni < 8; ++ni) {                                   \
                const int c = warpN + ni * 8 + (lane >> 2);                    \
                b[ni][0] = Bs[buf][kb * SPAD + c];                             \
                b[ni][1] = Bs[buf][(kb + 4) * SPAD + c];                       \
            }                                                                  \
            _Pragma("unroll")                                                  \
            for (int mi = 0; mi < 2; ++mi)                                     \
                _Pragma("unroll")                                              \
                for (int ni = 0; ni < 8; ++ni)                                 \
                    mma_tf32(acc[mi][ni], a[mi], b[ni]);                       \
        }                                                                      \
    }

template <bool GELU>
__global__ __launch_bounds__(256) void gemm_tf32(const float* __restrict__ A,
                                                 const float* __restrict__ B,
                                                 const float* __restrict__ bias,
                                                 float* __restrict__ C,
                                                 int M, int N, int K)
{
    __shared__ uint32_t As[2][16 * SPAD];
    __shared__ uint32_t Bs[2][16 * SPAD];
    const int tid = threadIdx.x, lane = tid & 31, w = tid >> 5;
    const int warpM = (w & 3) * 32, warpN = (w >> 2) * 64;
    const int m0 = blockIdx.y * 128, n0 = blockIdx.x * 128;
    const int arow = tid & 127, acol4 = tid >> 7;
    const int bk = tid >> 4,   bn4 = tid & 15;
    const float* Aglob = A + (size_t)(m0 + arow) * K + acol4 * 4;
    const float* Bglob = B + (size_t)bk * N + n0 + bn4 * 4;

    float acc[2][8][4] = {};

    LOAD_TILE(0, 0);
    __syncthreads();
    const int ntiles = K >> 4;
    for (int kt = 0; kt < ntiles; ++kt) {
        const int buf = kt & 1;
        if (kt + 1 < ntiles) LOAD_TILE((kt + 1) * 16, buf ^ 1);
        COMPUTE_TILE(buf);
        __syncthreads();
    }

#pragma unroll
    for (int mi = 0; mi < 2; ++mi) {
#pragma unroll
        for (int ni = 0; ni < 8; ++ni) {
            const int col = n0 + warpN + ni * 8 + 2 * (lane & 3);
            const float b0 = bias[col], b1 = bias[col + 1];
#pragma unroll
            for (int r = 0; r < 2; ++r) {
                const int row = m0 + warpM + mi * 16 + (lane >> 2) + 8 * r;
                float o0 = acc[mi][ni][2 * r + 0] + b0;
                float o1 = acc[mi][ni][2 * r + 1] + b1;
                if (GELU) { o0 = gelu_f(o0); o1 = gelu_f(o1); }
                *(float2*)&C[(size_t)row * N + col] = make_float2(o0, o1);
            }
        }
    }
}

// ---- split-K partial GEMM: blockIdx.z selects K-slice, plain partial store ----
__global__ __launch_bounds__(256) void gemm_tf32_part(const float* __restrict__ A,
                                                      const float* __restrict__ B,
                                                      float* __restrict__ Cpart,
                                                      int M, int N, int K, int Ksplit)
{
    __shared__ uint32_t As[2][16 * SPAD];
    __shared__ uint32_t Bs[2][16 * SPAD];
    const int tid = threadIdx.x, lane = tid & 31, w = tid >> 5;
    const int warpM = (w & 3) * 32, warpN = (w >> 2) * 64;
    const int m0 = blockIdx.y * 128, n0 = blockIdx.x * 128;
    const int koff = blockIdx.z * Ksplit;
    const int arow = tid & 127, acol4 = tid >> 7;
    const int bk = tid >> 4,   bn4 = tid & 15;
    const float* Aglob = A + (size_t)(m0 + arow) * K + koff + acol4 * 4;
    const float* Bglob = B + (size_t)(koff + bk) * N + n0 + bn4 * 4;

    float acc[2][8][4] = {};

    LOAD_TILE(0, 0);
    __syncthreads();
    const int ntiles = Ksplit >> 4;
    for (int kt = 0; kt < ntiles; ++kt) {
        const int buf = kt & 1;
        if (kt + 1 < ntiles) LOAD_TILE((kt + 1) * 16, buf ^ 1);
        COMPUTE_TILE(buf);
        __syncthreads();
    }

    float* Cp = Cpart + (size_t)blockIdx.z * M * N;
#pragma unroll
    for (int mi = 0; mi < 2; ++mi) {
#pragma unroll
        for (int ni = 0; ni < 8; ++ni) {
            const int col = n0 + warpN + ni * 8 + 2 * (lane & 3);
#pragma unroll
            for (int r = 0; r < 2; ++r) {
                const int row = m0 + warpM + mi * 16 + (lane >> 2) + 8 * r;
                *(float2*)&Cp[(size_t)row * N + col] =
                    make_float2(acc[mi][ni][2 * r + 0], acc[mi][ni][2 * r + 1]);
            }
        }
    }
}

// ---- reduce split-K partials: C = R + bias + sum(parts); N fixed at 768 ----
template <int S>
__global__ void reduce_kernel(const float* __restrict__ part, const float* __restrict__ bias,
                              const float* __restrict__ R, float* __restrict__ C)
{
    const int i = blockIdx.x * 256 + threadIdx.x;           // float4 index
    const int n4 = DD / 4;
    const int col = (i % n4) * 4;
    float4 acc = *(const float4*)&R[(size_t)i * 4];
    const float4 bv = *(const float4*)&bias[col];
    acc.x += bv.x; acc.y += bv.y; acc.z += bv.z; acc.w += bv.w;
#pragma unroll
    for (int s = 0; s < S; ++s) {
        const float4 p = *(const float4*)&part[(size_t)s * TT * DD + (size_t)i * 4];
        acc.x += p.x; acc.y += p.y; acc.z += p.z; acc.w += p.w;
    }
    *(float4*)&C[(size_t)i * 4] = acc;
}

// ---------------- pack fused weights [768, 3328] + bias ----------------
__global__ void pack_kernel(const float* __restrict__ qkvw, const float* __restrict__ geovw,
                            const float* __restrict__ w1w, const float* __restrict__ w2w,
                            const float* __restrict__ w1r, const float* __restrict__ w2r,
                            const float* __restrict__ gw,
                            const float* __restrict__ qkvb, const float* __restrict__ geovb,
                            float* __restrict__ Wout, float* __restrict__ bout)
{
    const int idx = blockIdx.x * 256 + threadIdx.x;
    if (idx >= DD * FD) return;
    const int k = idx / FD, c = idx % FD;
    float v = 0.f;
    if (c < 2304) v = qkvw[(size_t)k * 2304 + c];
    else if (c < 3072) v = geovw[(size_t)k * 768 + (c - 2304)];
    else {
        const int c2 = c - 3072;
        if (c2 < 48)       v = w1w[k * 48 + c2];
        else if (c2 < 96)  v = w2w[k * 48 + c2 - 48];
        else if (c2 < 144) v = w1r[k * 48 + c2 - 96];
        else if (c2 < 192) v = w2r[k * 48 + c2 - 144];
        else if (c2 < 204) v = gw[k * 12 + c2 - 192];
    }
    Wout[idx] = v;
    if (k == 0)
        bout[c] = (c < 2304) ? qkvb[c] : ((c < 3072) ? geovb[c - 2304] : 0.f);
}

// ---------------- exterior lines + J map + gate ----------------
__device__ __forceinline__ void ext6(const float* p, const float* q, float* L)
{
    L[0] = p[0] * q[1] - p[1] * q[0];
    L[1] = p[0] * q[2] - p[2] * q[0];
    L[2] = p[0] * q[3] - p[3] * q[0];
    L[3] = p[1] * q[2] - p[2] * q[1];
    L[4] = p[1] * q[3] - p[3] * q[1];
    L[5] = p[2] * q[3] - p[3] * q[2];
    float n2 = 0.f;
#pragma unroll
    for (int i = 0; i < 6; ++i) n2 += L[i] * L[i];
    const float inv = 1.f / fmaxf(sqrtf(n2), 1e-12f);
#pragma unroll
    for (int i = 0; i < 6; ++i) L[i] *= inv;
}

__global__ void lines_kernel(const float* __restrict__ fused, const float* __restrict__ gb,
                             float* __restrict__ rlo, float* __restrict__ jwo,
                             float* __restrict__ gateo)
{
    const int idx = blockIdx.x * 256 + threadIdx.x;
    if (idx >= TT * NH) return;
    const int t = idx / NH, h = idx % NH;
    const float* Pt = fused + (size_t)t * FD + 3072;
    float p1[4], p2[4], L[6];
#pragma unroll
    for (int e = 0; e < 4; ++e) {
        p1[e] = (t > 0) ? fused[(size_t)(t - 1) * FD + 3072 + h * 4 + e] : 0.f;
        p2[e] = Pt[48 + h * 4 + e];
    }
    ext6(p1, p2, L);
    const size_t base = (size_t)t * (NH * 6) + h * 6;
    jwo[base + 0] =  L[5]; jwo[base + 1] = -L[4]; jwo[base + 2] =  L[3];
    jwo[base + 3] =  L[2]; jwo[base + 4] = -L[1]; jwo[base + 5] =  L[0];
#pragma unroll
    for (int e = 0; e < 4; ++e) { p1[e] = Pt[96 + h * 4 + e]; p2[e] = Pt[144 + h * 4 + e]; }
    ext6(p1, p2, L);
#pragma unroll
    for (int i = 0; i < 6; ++i) rlo[base + i] = L[i];
    if (h == 0) {
        float acc = 0.f;
#pragma unroll
        for (int j = 0; j < NH; ++j) acc += 1.f / (1.f + expf(-(Pt[192 + j] + gb[j])));
        gateo[t] = acc * (1.f / 12.f);
    }
}

// ---------------- fused dual-path causal flash attention (split-tf32 mma) --------
// grid (32, 12), 128 threads = 4 warps; each warp: m16 x n64 via m16n8k8.
// QK^T uses 3-term split tf32 (Qhi*Khi + Qlo*Khi + Qhi*Klo); geo logits likewise.
// Q and RL fragments live in registers (hi+lo); P buffer aliases the K tile.
#define AST 76

__device__ __forceinline__ void softmax_update_mma(float S[8][4], float* m, float* l,
                                                   float O[8][4], uint32_t* sP,
                                                   int warpM, int g, int t)
{
    float mx0 = -1e30f, mx1 = -1e30f;
#pragma unroll
    for (int ni = 0; ni < 8; ++ni) {
        mx0 = fmaxf(mx0, fmaxf(S[ni][0], S[ni][1]));
        mx1 = fmaxf(mx1, fmaxf(S[ni][2], S[ni][3]));
    }
#pragma unroll
    for (int o = 1; o <= 2; o <<= 1) {
        mx0 = fmaxf(mx0, __shfl_xor_sync(0xffffffffu, mx0, o));
        mx1 = fmaxf(mx1, __shfl_xor_sync(0xffffffffu, mx1, o));
    }
    const float mn0 = fmaxf(m[0], mx0), mn1 = fmaxf(m[1], mx1);
    const float c0 = __expf(m[0] - mn0), c1 = __expf(m[1] - mn1);
    m[0] = mn0; m[1] = mn1;
    float s0 = 0.f, s1 = 0.f;
#pragma unroll
    for (int ni = 0; ni < 8; ++ni) {
        const float p0 = __expf(S[ni][0] - mn0), p1 = __expf(S[ni][1] - mn0);
        const float p2 = __expf(S[ni][2] - mn1), p3 = __expf(S[ni][3] - mn1);
        s0 += p0 + p1; s1 += p2 + p3;
        const int sc = ni * 8 + 2 * t;
        sP[(sc    ) * AST + warpM + g    ] = f2tf32(p0);
        sP[(sc + 1) * AST + warpM + g    ] = f2tf32(p1);
        sP[(sc    ) * AST + warpM + g + 8] = f2tf32(p2);
        sP[(sc + 1) * AST + warpM + g + 8] = f2tf32(p3);
        O[ni][0] *= c0; O[ni][1] *= c0; O[ni][2] *= c1; O[ni][3] *= c1;
    }
#pragma unroll
    for (int o = 1; o <= 2; o <<= 1) {
        s0 += __shfl_xor_sync(0xffffffffu, s0, o);
        s1 += __shfl_xor_sync(0xffffffffu, s1, o);
    }
    l[0] = l[0] * c0 + s0;
    l[1] = l[1] * c1 + s1;
}

__global__ __launch_bounds__(128) void attn_kernel(const float* __restrict__ fused,
                                                   const float* __restrict__ rl,
                                                   const float* __restrict__ jwg,
                                                   const float* __restrict__ gate,
                                                   const float* __restrict__ inc,
                                                   float* __restrict__ comb)
{
    extern __shared__ uint32_t sm[];
    uint32_t* sK   = sm;                // [d][s] 64xAST (aliased by P [s][q] after QK)
    uint32_t* sKlo = sK   + 64 * AST;   // [d][s]
    uint32_t* sV   = sKlo + 64 * AST;   // [s][d]
    uint32_t* sGV  = sV   + 64 * AST;   // [s][d]
    uint32_t* sJWh = sGV  + 64 * AST;   // [i][s] 8xAST (rows 6,7 zero)
    uint32_t* sJWl = sJWh + 8 * AST;    // [i][s] 8xAST (rows 6,7 zero)
    uint32_t* sP   = sK;                // alias

    const int h = blockIdx.y;
    const int qb = gridDim.x - 1 - blockIdx.x;  // heavy tiles first
    const int qt0 = qb * 64;
    const int tid = threadIdx.x;
    const int lane = tid & 31, w = tid >> 5;
    const int g = lane >> 2, t = lane & 3;
    const int warpM = w * 16;
    const int lr = tid >> 1, d0 = (tid & 1) * 32;

    for (int i = tid; i < 2 * AST; i += 128) { sJWh[6 * AST + i] = 0; sJWl[6 * AST + i] = 0; }

    // ---- Q fragments (hi/lo) in registers, loaded straight from global ----
    uint32_t qh[8][4], ql[8][4];
    {
        const float* q0 = fused + (size_t)(qt0 + warpM + g) * FD + h * DHH;
        const float* q1 = q0 + (size_t)8 * FD;
#pragma unroll
        for (int k8 = 0; k8 < 8; ++k8) {
            const int kk = k8 * 8 + t;
            const float v0 = q0[kk], v1 = q1[kk], v2 = q0[kk + 4], v3 = q1[kk + 4];
            qh[k8][0] = f2tf32(v0); ql[k8][0] = f2tf32(v0 - __uint_as_float(qh[k8][0]));
            qh[k8][1] = f2tf32(v1); ql[k8][1] = f2tf32(v1 - __uint_as_float(qh[k8][1]));
            qh[k8][2] = f2tf32(v2); ql[k8][2] = f2tf32(v2 - __uint_as_float(qh[k8][2]));
            qh[k8][3] = f2tf32(v3); ql[k8][3] = f2tf32(v3 - __uint_as_float(qh[k8][3]));
        }
    }
    // ---- RL fragments (hi/lo) in registers ----
    uint32_t rlh[4], rll[4];
    {
        const float* r0p = rl + (size_t)(qt0 + warpM + g) * (NH * 6) + h * 6;
        const float* r1p = r0p + (size_t)8 * (NH * 6);
        const float v0 = r0p[t], v1 = r1p[t];
        const float v2 = (t < 2) ? r0p[t + 4] : 0.f;
        const float v3 = (t < 2) ? r1p[t + 4] : 0.f;
        rlh[0] = f2tf32(v0); rll[0] = f2tf32(v0 - __uint_as_float(rlh[0]));
        rlh[1] = f2tf32(v1); rll[1] = f2tf32(v1 - __uint_as_float(rlh[1]));
        rlh[2] = f2tf32(v2); rll[2] = f2tf32(v2 - __uint_as_float(rlh[2]));
        rlh[3] = f2tf32(v3); rll[3] = f2tf32(v3 - __uint_as_float(rlh[3]));
    }
    const float iscale = inc[h];

    float Os[8][4] = {}, Og[8][4] = {};
    float ms[2] = {-1e30f, -1e30f}, mg[2] = {-1e30f, -1e30f}, ls[2] = {}, lg[2] = {};

    for (int kt0 = 0; kt0 <= qt0; kt0 += 64) {
        __syncthreads();   // prior-iter sP/sGV reads done before tile overwrite
        { // load K hi/lo (transposed), V/GV natural, JW hi/lo
            const float* ksrc = fused + (size_t)(kt0 + lr) * FD +  DD + h * DHH + d0;
            const float* vsrc = fused + (size_t)(kt0 + lr) * FD + 2 * DD + h * DHH + d0;
            const float* gsrc = fused + (size_t)(kt0 + lr) * FD + 3 * DD + h * DHH + d0;
#pragma unroll
            for (int u = 0; u < 8; ++u) {
                const int d = d0 + 4 * u;
                const float4 kv = *(const float4*)(ksrc + 4 * u);
                uint32_t h0 = f2tf32(kv.x), h1 = f2tf32(kv.y), h2 = f2tf32(kv.z), h3 = f2tf32(kv.w);
                sK[(d + 0) * AST + lr] = h0;
                sK[(d + 1) * AST + lr] = h1;
                sK[(d + 2) * AST + lr] = h2;
                sK[(d + 3) * AST + lr] = h3;
                sKlo[(d + 0) * AST + lr] = f2tf32(kv.x - __uint_as_float(h0));
                sKlo[(d + 1) * AST + lr] = f2tf32(kv.y - __uint_as_float(h1));
                sKlo[(d + 2) * AST + lr] = f2tf32(kv.z - __uint_as_float(h2));
                sKlo[(d + 3) * AST + lr] = f2tf32(kv.w - __uint_as_float(h3));
                const float4 vv = *(const float4*)(vsrc + 4 * u);
                uint4 pv; pv.x = f2tf32(vv.x); pv.y = f2tf32(vv.y);
                pv.z = f2tf32(vv.z); pv.w = f2tf32(vv.w);
                *(uint4*)&sV[lr * AST + d] = pv;
                const float4 gv = *(const float4*)(gsrc + 4 * u);
                uint4 pg; pg.x = f2tf32(gv.x); pg.y = f2tf32(gv.y);
                pg.z = f2tf32(gv.z); pg.w = f2tf32(gv.w);
                *(uint4*)&sGV[lr * AST + d] = pg;
            }
        }
        if (tid < 64) {
#pragma unroll
            for (int i = 0; i < 6; ++i) {
                const float v = jwg[(size_t)(kt0 + tid) * (NH * 6) + h * 6 + i];
                const uint32_t hi = f2tf32(v);
                sJWh[i * AST + tid] = hi;
                sJWl[i * AST + tid] = f2tf32(v - __uint_as_float(hi));
            }
        }
        __syncthreads();
        const bool diag = (kt0 == qt0);

        // ==== std path: S = Q K^T * 1/8 (3-term split tf32) ====
        float S[8][4] = {};
#pragma unroll
        for (int k8 = 0; k8 < 8; ++k8) {
            const int kk = k8 * 8 + t;
#pragma unroll
            for (int ni = 0; ni < 8; ++ni) {
                const int c = ni * 8 + g;
                uint32_t bh[2], bl[2];
                bh[0] = sK[kk * AST + c];
                bh[1] = sK[(kk + 4) * AST + c];
                bl[0] = sKlo[kk * AST + c];
                bl[1] = sKlo[(kk + 4) * AST + c];
                mma_tf32(S[ni], qh[k8], bh);
                mma_tf32(S[ni], ql[k8], bh);
                mma_tf32(S[ni], qh[k8], bl);
            }
        }
#pragma unroll
        for (int ni = 0; ni < 8; ++ni) {
            const int sc = ni * 8 + 2 * t;
#pragma unroll
            for (int j = 0; j < 4; ++j) S[ni][j] *= 0.125f;
            if (diag) {
                const int r0 = warpM + g, r1 = r0 + 8;
                if (sc     > r0) S[ni][0] = -1e30f;
                if (sc + 1 > r0) S[ni][1] = -1e30f;
                if (sc     > r1) S[ni][2] = -1e30f;
                if (sc + 1 > r1) S[ni][3] = -1e30f;
            }
        }
        __syncthreads();   // all warps done reading sK/sKlo before P overwrites sK
        softmax_update_mma(S, ms, ls, Os, sP, warpM, g, t);
        __syncwarp();
#pragma unroll
        for (int k8 = 0; k8 < 8; ++k8) {
            const int kk = k8 * 8 + t;
            uint32_t a[4], b[2];
            a[0] = sP[kk * AST + warpM + g];
            a[1] = sP[kk * AST + warpM + g + 8];
            a[2] = sP[(kk + 4) * AST + warpM + g];
            a[3] = sP[(kk + 4) * AST + warpM + g + 8];
#pragma unroll
            for (int ni = 0; ni < 8; ++ni) {
                b[0] = sV[kk * AST + ni * 8 + g];
                b[1] = sV[(kk + 4) * AST + ni * 8 + g];
                mma_tf32(Os[ni], a, b);
            }
        }
        __syncwarp();

        // ==== geo path: S = RL . JW * inc_scale (3-term split, k=8 padded) ====
#pragma unroll
        for (int ni = 0; ni < 8; ++ni)
#pragma unroll
            for (int j = 0; j < 4; ++j) S[ni][j] = 0.f;
#pragma unroll
        for (int ni = 0; ni < 8; ++ni) {
            const int c = ni * 8 + g;
            uint32_t bh[2], bl[2];
            bh[0] = sJWh[t * AST + c];
            bh[1] = sJWh[(t + 4) * AST + c];
            bl[0] = sJWl[t * AST + c];
            bl[1] = sJWl[(t + 4) * AST + c];
            mma_tf32(S[ni], rlh, bh);
            mma_tf32(S[ni], rll, bh);
            mma_tf32(S[ni], rlh, bl);
        }
#pragma unroll
        for (int ni = 0; ni < 8; ++ni) {
            const int sc = ni * 8 + 2 * t;
#pragma unroll
            for (int j = 0; j < 4; ++j) S[ni][j] *= iscale;
            if (diag) {
                const int r0 = warpM + g, r1 = r0 + 8;
                if (sc     > r0) S[ni][0] = -1e30f;
                if (sc + 1 > r0) S[ni][1] = -1e30f;
                if (sc     > r1) S[ni][2] = -1e30f;
                if (sc + 1 > r1) S[ni][3] = -1e30f;
            }
        }
        // P region writes are warp-column-private from here on: no block barrier
        softmax_update_mma(S, mg, lg, Og, sP, warpM, g, t);
        __syncwarp();
#pragma unroll
        for (int k8 = 0; k8 < 8; ++k8) {
            const int kk = k8 * 8 + t;
            uint32_t a[4], b[2];
            a[0] = sP[kk * AST + warpM + g];
            a[1] = sP[kk * AST + warpM + g + 8];
            a[2] = sP[(kk + 4) * AST + warpM + g];
            a[3] = sP[(kk + 4) * AST + warpM + g + 8];
#pragma unroll
            for (int ni = 0; ni < 8; ++ni) {
                b[0] = sGV[kk * AST + ni * 8 + g];
                b[1] = sGV[(kk + 4) * AST + ni * 8 + g];
                mma_tf32(Og[ni], a, b);
            }
        }
        __syncwarp();
    }

    // ---- finalize: combined = (1-g)*std/ls + g*geo/lg ----
    const int r0 = qt0 + warpM + g, r1 = r0 + 8;
    const float g0 = gate[r0], g1 = gate[r1];
    const float as0 = (1.f - g0) / ls[0], ag0 = g0 / lg[0];
    const float as1 = (1.f - g1) / ls[1], ag1 = g1 / lg[1];
#pragma unroll
    for (int ni = 0; ni < 8; ++ni) {
        const int d = ni * 8 + 2 * t;
        float2 o0 = make_float2(Os[ni][0] * as0 + Og[ni][0] * ag0,
                                Os[ni][1] * as0 + Og[ni][1] * ag0);
        float2 o1 = make_float2(Os[ni][2] * as1 + Og[ni][2] * ag1,
                                Os[ni][3] * as1 + Og[ni][3] * ag1);
        *(float2*)&comb[(size_t)r0 * DD + h * DHH + d] = o0;
        *(float2*)&comb[(size_t)r1 * DD + h * DHH + d] = o1;
    }
}

// ---------------- host ----------------
extern "C" void kernel_launch(void* const* d_in, const int* in_sizes, int n_in,
                              void* d_out, int out_size)
{
    (void)in_sizes; (void)n_in; (void)out_size;
    const float* x     = (const float*)d_in[0];
    const float* ln1g  = (const float*)d_in[1];
    const float* ln1b  = (const float*)d_in[2];
    const float* qkvw  = (const float*)d_in[3];
    const float* qkvb  = (const float*)d_in[4];
    const float* w1w   = (const float*)d_in[5];
    const float* w2w   = (const float*)d_in[6];
    const float* w1r   = (const float*)d_in[7];
    const float* w2r   = (const float*)d_in[8];
    const float* geovw = (const float*)d_in[9];
    const float* geovb = (const float*)d_in[10];
    const float* gatew = (const float*)d_in[11];
    const float* gateb = (const float*)d_in[12];
    const float* incs  = (const float*)d_in[13];
    const float* outw  = (const float*)d_in[14];
    const float* outb  = (const float*)d_in[15];
    const float* ln2g  = (const float*)d_in[16];
    const float* ln2b  = (const float*)d_in[17];
    const float* fcw   = (const float*)d_in[18];
    const float* fcb   = (const float*)d_in[19];
    const float* projw = (const float*)d_in[20];
    const float* projb = (const float*)d_in[21];
    float* out = (float*)d_out;

    float *xn, *fz, *wp, *bp, *rlp, *jwp, *gatep, *combp, *hp, *mp, *actp, *partp;
    cudaGetSymbolAddress((void**)&xn,    g_xn);
    cudaGetSymbolAddress((void**)&fz,    g_fused);
    cudaGetSymbolAddress((void**)&wp,    g_wpack);
    cudaGetSymbolAddress((void**)&bp,    g_bpack);
    cudaGetSymbolAddress((void**)&rlp,   g_rl);
    cudaGetSymbolAddress((void**)&jwp,   g_jw);
    cudaGetSymbolAddress((void**)&gatep, g_gate);
    cudaGetSymbolAddress((void**)&combp, g_comb);
    cudaGetSymbolAddress((void**)&hp,    g_h);
    cudaGetSymbolAddress((void**)&mp,    g_m);
    cudaGetSymbolAddress((void**)&actp,  g_act);
    cudaGetSymbolAddress((void**)&partp, g_part);

    const int smem_attn = (4 * 64 * AST + 2 * 8 * AST) * (int)sizeof(uint32_t);
    cudaFuncSetAttribute(attn_kernel, cudaFuncAttributeMaxDynamicSharedMemorySize, smem_attn);

    // 1. xn = LN1(x)
    ln_kernel<<<TT, 256>>>(x, ln1g, ln1b, xn);
    // 2. pack fused weights + bias
    pack_kernel<<<(DD * FD + 255) / 256, 256>>>(qkvw, geovw, w1w, w2w, w1r, w2r, gatew,
                                                qkvb, geovb, wp, bp);
    // 3. fused = xn @ [qkv_w | geov_w | wcat] + bias   (2048 x 3328 x 768)
    gemm_tf32<false><<<dim3(26, 16), 256>>>(xn, wp, bp, fz, TT, FD, DD);
    // 4. exterior lines + J + gate
    lines_kernel<<<(TT * NH + 255) / 256, 256>>>(fz, gateb, rlp, jwp, gatep);
    // 5. fused dual-path attention -> combined
    attn_kernel<<<dim3(32, NH), 128, smem_attn>>>(fz, rlp, jwp, gatep, incs, combp);
    // 6. h = x + combined @ out_w + b  (split-K 2, 2-pass deterministic)
    gemm_tf32_part<<<dim3(6, 16, 2), 256>>>(combp, outw, partp, TT, DD, DD, 384);
    reduce_kernel<2><<<TT * DD / 4 / 256, 256>>>(partp, outb, x, hp);
    // 7. m = LN2(h)
    ln_kernel<<<TT, 256>>>(hp, ln2g, ln2b, mp);
    // 8. act = gelu(m @ fc_w + b)
    gemm_tf32<true><<<dim3(24, 16), 256>>>(mp, fcw, fcb, actp, TT, 4 * DD, DD);
    // 9. out = h + act @ proj_w + b  (split-K 4, 2-pass deterministic)
    gemm_tf32_part<<<dim3(6, 16, 4), 256>>>(actp, projw, partp, TT, DD, 4 * DD, 768);
    reduce_kernel<4><<<TT * DD / 4 / 256, 256>>>(partp, projb, hp, out);
}

// round 13
// speedup vs baseline: 2.8539x; 1.1448x over previous
#include <cuda_runtime.h>
#include <math.h>
#include <stdint.h>

#define TT 2048
#define DD 768
#define NH 12
#define DHH 64
#define FD 3328            // fused GEMM width: 2304 qkv + 768 geov + 256 smallproj

// ---------------- scratch (device globals, no allocation) ----------------
__device__ float g_xn[TT * DD];            // ln1(x)
__device__ float g_fused[TT * FD];         // [qkv | geov | P]
__device__ float g_wpack[DD * FD];         // packed weights
__device__ float g_bpack[FD];              // packed bias
__device__ float g_rl[TT * NH * 6];        // read lines (normalized)
__device__ float g_jw[TT * NH * 6];        // J @ write lines
__device__ float g_gate[TT];               // gate scalar per token
__device__ float g_comb[TT * DD];          // combined attention output
__device__ float g_h[TT * DD];             // h = x + attn
__device__ float g_m[TT * DD];             // ln2(h)
__device__ float g_act[TT * 4 * DD];       // gelu(fc)
__device__ float g_part[4 * TT * DD];      // split-K partials

// ---------------- helpers ----------------
__device__ __forceinline__ uint32_t f2tf32(float x)
{
    uint32_t r;
    asm("cvt.rna.tf32.f32 %0, %1;" : "=r"(r) : "f"(x));
    return r;
}

__device__ __forceinline__ float gelu_f(float x)
{
    const float x3 = x * x * x;
    return 0.5f * x * (1.f + tanhf(0.7978845608028654f * (x + 0.044715f * x3)));
}

__device__ __forceinline__ void mma_tf32(float* d, const uint32_t* a, const uint32_t* b)
{
    asm volatile("mma.sync.aligned.m16n8k8.row.col.f32.tf32.tf32.f32 "
                 "{%0,%1,%2,%3}, {%4,%5,%6,%7}, {%8,%9}, {%0,%1,%2,%3};"
                 : "+f"(d[0]), "+f"(d[1]), "+f"(d[2]), "+f"(d[3])
                 : "r"(a[0]), "r"(a[1]), "r"(a[2]), "r"(a[3]), "r"(b[0]), "r"(b[1]));
}

__device__ __forceinline__ uint32_t smem_u32(const void* p)
{
    return (uint32_t)__cvta_generic_to_shared(p);
}

__device__ __forceinline__ void cp16(uint32_t saddr, const void* g)
{
    asm volatile("cp.async.cg.shared.global [%0], [%1], 16;" :: "r"(saddr), "l"(g));
}

// ---------------- LayerNorm ----------------
__global__ void ln_kernel(const float* __restrict__ x, const float* __restrict__ g,
                          const float* __restrict__ b, float* __restrict__ y)
{
    const int t = blockIdx.x, tid = threadIdx.x;
    const float* xr = x + (size_t)t * DD;
    float v[3];
    float s = 0.f, s2 = 0.f;
#pragma unroll
    for (int i = 0; i < 3; ++i) {
        v[i] = xr[tid + i * 256];
        s += v[i];
        s2 += v[i] * v[i];
    }
    __shared__ float rs[8], rs2[8];
#pragma unroll
    for (int o = 16; o > 0; o >>= 1) {
        s  += __shfl_xor_sync(0xffffffffu, s, o);
        s2 += __shfl_xor_sync(0xffffffffu, s2, o);
    }
    const int w = tid >> 5, l = tid & 31;
    if (l == 0) { rs[w] = s; rs2[w] = s2; }
    __syncthreads();
    s = 0.f; s2 = 0.f;
#pragma unroll
    for (int i = 0; i < 8; ++i) { s += rs[i]; s2 += rs2[i]; }
    const float mean = s * (1.f / 768.f);
    const float var  = s2 * (1.f / 768.f) - mean * mean;
    const float rstd = rsqrtf(var + 1e-5f);
#pragma unroll
    for (int i = 0; i < 3; ++i) {
        const int c = tid + i * 256;
        y[(size_t)t * DD + c] = (v[i] - mean) * rstd * g[c] + b[c];
    }
}

// ======== tf32 tensor-core GEMM v2: 128x128x16, cp.async 4-stage pipeline ========
// A[M,K] row-major (fp32 in smem, cvt at frag load), B[K,N] row-major.
// smem: A stage [128][20] (pad), B stage [16][136] (pad). 8 warps 4Mx2N,
// warp tile m32 x n64 via m16n8k8.
#define GAPAD 20
#define GBPAD 136
#define GASTG (128 * GAPAD)     // floats per A stage
#define GBSTG (16 * GBPAD)      // floats per B stage
#define GSMEM ((4 * GASTG + 4 * GBSTG) * 4)   // bytes

// issue one stage's loads: 2 A chunks + 2 B chunks per thread, then commit
#define G_ISSUE(stg, kt)                                                          \
    {                                                                             \
        const int kof = (kt) * 16;                                                \
        uint32_t da = saA + ((stg) * GASTG + arow * GAPAD + acol) * 4;            \
        const float* ga = Aglob + kof + acol;                                     \
        cp16(da, ga);                                                             \
        cp16(da + 16, ga + 4);                                                    \
        uint32_t db = saB + ((stg) * GBSTG + brow * GBPAD + bcol) * 4;            \
        const float* gb = Bglob + (size_t)(kof + brow) * N + bcol;                \
        cp16(db, gb);                                                             \
        cp16(db + 16, gb + 4);                                                    \
        asm volatile("cp.async.commit_group;" ::: "memory");                      \
    }

#define G_COMPUTE(stg)                                                            \
    {                                                                             \
        const float* Af = smA + (stg) * GASTG;                                    \
        const float* Bf = smB + (stg) * GBSTG;                                    \
        _Pragma("unroll")                                                         \
        for (int ks = 0; ks < 2; ++ks) {                                          \
            const int kb = ks * 8 + t;                                            \
            uint32_t a[2][4], b[8][2];                                            \
            _Pragma("unroll")                                                     \
            for (int mi = 0; mi < 2; ++mi) {                                      \
                const int r = warpM + mi * 16 + g;                                \
                a[mi][0] = f2tf32(Af[r * GAPAD + kb]);                            \
                a[mi][1] = f2tf32(Af[(r + 8) * GAPAD + kb]);                      \
                a[mi][2] = f2tf32(Af[r * GAPAD + kb + 4]);                        \
                a[mi][3] = f2tf32(Af[(r + 8) * GAPAD + kb + 4]);                  \
            }                                                                     \
            _Pragma("unroll")                                                     \
            for (int ni = 0; ni < 8; ++ni) {                                      \
                const int c = warpN + ni * 8 + g;                                 \
                b[ni][0] = f2tf32(Bf[kb * GBPAD + c]);                            \
                b[ni][1] = f2tf32(Bf[(kb + 4) * GBPAD + c]);                      \
            }                                                                     \
            _Pragma("unroll")                                                     \
            for (int mi = 0; mi < 2; ++mi)                                        \
                _Pragma("unroll")                                                 \
                for (int ni = 0; ni < 8; ++ni)                                    \
                    mma_tf32(acc[mi][ni], a[mi], b[ni]);                          \
        }                                                                         \
    }

#define G_PRO_MAIN(NT)                                                            \
    G_ISSUE(0, 0); G_ISSUE(1, 1); G_ISSUE(2, 2);                                  \
    for (int kt = 0; kt < (NT); ++kt) {                                           \
        asm volatile("cp.async.wait_group 2;" ::: "memory");                      \
        __syncthreads();                                                          \
        if (kt + 3 < (NT)) { G_ISSUE((kt + 3) & 3, kt + 3); }                     \
        G_COMPUTE(kt & 3);                                                        \
    }

template <bool GELU>
__global__ __launch_bounds__(256, 2) void gemm_tf32(const float* __restrict__ A,
                                                    const float* __restrict__ B,
                                                    const float* __restrict__ bias,
                                                    float* __restrict__ C,
                                                    int M, int N, int K)
{
    extern __shared__ float dsm[];
    float* smA = dsm;
    float* smB = dsm + 4 * GASTG;
    const uint32_t saA = smem_u32(smA), saB = smem_u32(smB);
    const int tid = threadIdx.x, lane = tid & 31, w = tid >> 5;
    const int g = lane >> 2, t = lane & 3;
    const int warpM = (w & 3) * 32, warpN = (w >> 2) * 64;
    const int m0 = blockIdx.y * 128, n0 = blockIdx.x * 128;
    const int arow = tid >> 1, acol = (tid & 1) * 8;
    const int brow = tid >> 4, bcol = (tid & 15) * 8;
    const float* Aglob = A + (size_t)(m0 + arow) * K;
    const float* Bglob = B + n0;

    float acc[2][8][4] = {};
    const int ntiles = K >> 4;
    G_PRO_MAIN(ntiles)

#pragma unroll
    for (int mi = 0; mi < 2; ++mi) {
#pragma unroll
        for (int ni = 0; ni < 8; ++ni) {
            const int col = n0 + warpN + ni * 8 + 2 * t;
            const float b0 = bias[col], b1 = bias[col + 1];
#pragma unroll
            for (int r = 0; r < 2; ++r) {
                const int row = m0 + warpM + mi * 16 + g + 8 * r;
                float o0 = acc[mi][ni][2 * r + 0] + b0;
                float o1 = acc[mi][ni][2 * r + 1] + b1;
                if (GELU) { o0 = gelu_f(o0); o1 = gelu_f(o1); }
                *(float2*)&C[(size_t)row * N + col] = make_float2(o0, o1);
            }
        }
    }
}

// ---- split-K partial GEMM (same pipeline): blockIdx.z selects K-slice ----
__global__ __launch_bounds__(256, 2) void gemm_tf32_part(const float* __restrict__ A,
                                                         const float* __restrict__ B,
                                                         float* __restrict__ Cpart,
                                                         int M, int N, int K, int Ksplit)
{
    extern __shared__ float dsm[];
    float* smA = dsm;
    float* smB = dsm + 4 * GASTG;
    const uint32_t saA = smem_u32(smA), saB = smem_u32(smB);
    const int tid = threadIdx.x, lane = tid & 31, w = tid >> 5;
    const int g = lane >> 2, t = lane & 3;
    const int warpM = (w & 3) * 32, warpN = (w >> 2) * 64;
    const int m0 = blockIdx.y * 128, n0 = blockIdx.x * 128;
    const int koff = blockIdx.z * Ksplit;
    const int arow = tid >> 1, acol = (tid & 1) * 8;
    const int brow = tid >> 4, bcol = (tid & 15) * 8;
    const float* Aglob = A + (size_t)(m0 + arow) * K + koff;
    const float* Bglob = B + (size_t)koff * N + n0;

    float acc[2][8][4] = {};
    const int ntiles = Ksplit >> 4;
    G_PRO_MAIN(ntiles)

    float* Cp = Cpart + (size_t)blockIdx.z * M * N;
#pragma unroll
    for (int mi = 0; mi < 2; ++mi) {
#pragma unroll
        for (int ni = 0; ni < 8; ++ni) {
            const int col = n0 + warpN + ni * 8 + 2 * t;
#pragma unroll
            for (int r = 0; r < 2; ++r) {
                const int row = m0 + warpM + mi * 16 + g + 8 * r;
                *(float2*)&Cp[(size_t)row * N + col] =
                    make_float2(acc[mi][ni][2 * r + 0], acc[mi][ni][2 * r + 1]);
            }
        }
    }
}

// ---- reduce split-K partials: C = R + bias + sum(parts); N fixed at 768 ----
template <int S>
__global__ void reduce_kernel(const float* __restrict__ part, const float* __restrict__ bias,
                              const float* __restrict__ R, float* __restrict__ C)
{
    const int i = blockIdx.x * 256 + threadIdx.x;           // float4 index
    const int n4 = DD / 4;
    const int col = (i % n4) * 4;
    float4 acc = *(const float4*)&R[(size_t)i * 4];
    const float4 bv = *(const float4*)&bias[col];
    acc.x += bv.x; acc.y += bv.y; acc.z += bv.z; acc.w += bv.w;
#pragma unroll
    for (int s = 0; s < S; ++s) {
        const float4 p = *(const float4*)&part[(size_t)s * TT * DD + (size_t)i * 4];
        acc.x += p.x; acc.y += p.y; acc.z += p.z; acc.w += p.w;
    }
    *(float4*)&C[(size_t)i * 4] = acc;
}

// ---------------- pack fused weights [768, 3328] + bias ----------------
__global__ void pack_kernel(const float* __restrict__ qkvw, const float* __restrict__ geovw,
                            const float* __restrict__ w1w, const float* __restrict__ w2w,
                            const float* __restrict__ w1r, const float* __restrict__ w2r,
                            const float* __restrict__ gw,
                            const float* __restrict__ qkvb, const float* __restrict__ geovb,
                            float* __restrict__ Wout, float* __restrict__ bout)
{
    const int idx = blockIdx.x * 256 + threadIdx.x;
    if (idx >= DD * FD) return;
    const int k = idx / FD, c = idx % FD;
    float v = 0.f;
    if (c < 2304) v = qkvw[(size_t)k * 2304 + c];
    else if (c < 3072) v = geovw[(size_t)k * 768 + (c - 2304)];
    else {
        const int c2 = c - 3072;
        if (c2 < 48)       v = w1w[k * 48 + c2];
        else if (c2 < 96)  v = w2w[k * 48 + c2 - 48];
        else if (c2 < 144) v = w1r[k * 48 + c2 - 96];
        else if (c2 < 192) v = w2r[k * 48 + c2 - 144];
        else if (c2 < 204) v = gw[k * 12 + c2 - 192];
    }
    Wout[idx] = v;
    if (k == 0)
        bout[c] = (c < 2304) ? qkvb[c] : ((c < 3072) ? geovb[c - 2304] : 0.f);
}

// ---------------- exterior lines + J map + gate ----------------
__device__ __forceinline__ void ext6(const float* p, const float* q, float* L)
{
    L[0] = p[0] * q[1] - p[1] * q[0];
    L[1] = p[0] * q[2] - p[2] * q[0];
    L[2] = p[0] * q[3] - p[3] * q[0];
    L[3] = p[1] * q[2] - p[2] * q[1];
    L[4] = p[1] * q[3] - p[3] * q[1];
    L[5] = p[2] * q[3] - p[3] * q[2];
    float n2 = 0.f;
#pragma unroll
    for (int i = 0; i < 6; ++i) n2 += L[i] * L[i];
    const float inv = 1.f / fmaxf(sqrtf(n2), 1e-12f);
#pragma unroll
    for (int i = 0; i < 6; ++i) L[i] *= inv;
}

__global__ void lines_kernel(const float* __restrict__ fused, const float* __restrict__ gb,
                             float* __restrict__ rlo, float* __restrict__ jwo,
                             float* __restrict__ gateo)
{
    const int idx = blockIdx.x * 256 + threadIdx.x;
    if (idx >= TT * NH) return;
    const int t = idx / NH, h = idx % NH;
    const float* Pt = fused + (size_t)t * FD + 3072;
    float p1[4], p2[4], L[6];
#pragma unroll
    for (int e = 0; e < 4; ++e) {
        p1[e] = (t > 0) ? fused[(size_t)(t - 1) * FD + 3072 + h * 4 + e] : 0.f;
        p2[e] = Pt[48 + h * 4 + e];
    }
    ext6(p1, p2, L);
    const size_t base = (size_t)t * (NH * 6) + h * 6;
    jwo[base + 0] =  L[5]; jwo[base + 1] = -L[4]; jwo[base + 2] =  L[3];
    jwo[base + 3] =  L[2]; jwo[base + 4] = -L[1]; jwo[base + 5] =  L[0];
#pragma unroll
    for (int e = 0; e < 4; ++e) { p1[e] = Pt[96 + h * 4 + e]; p2[e] = Pt[144 + h * 4 + e]; }
    ext6(p1, p2, L);
#pragma unroll
    for (int i = 0; i < 6; ++i) rlo[base + i] = L[i];
    if (h == 0) {
        float acc = 0.f;
#pragma unroll
        for (int j = 0; j < NH; ++j) acc += 1.f / (1.f + expf(-(Pt[192 + j] + gb[j])));
        gateo[t] = acc * (1.f / 12.f);
    }
}

// ---------------- fused dual-path causal flash attention (split-tf32 mma) --------
// grid (32, 12), 128 threads = 4 warps; each warp: m16 x n64 via m16n8k8.
// QK^T uses 3-term split tf32 (Qhi*Khi + Qlo*Khi + Qhi*Klo); geo logits likewise.
// Q and RL fragments live in registers (hi+lo); P buffer aliases the K tile.
#define AST 76

__device__ __forceinline__ void softmax_update_mma(float S[8][4], float* m, float* l,
                                                   float O[8][4], uint32_t* sP,
                                                   int warpM, int g, int t)
{
    float mx0 = -1e30f, mx1 = -1e30f;
#pragma unroll
    for (int ni = 0; ni < 8; ++ni) {
        mx0 = fmaxf(mx0, fmaxf(S[ni][0], S[ni][1]));
        mx1 = fmaxf(mx1, fmaxf(S[ni][2], S[ni][3]));
    }
#pragma unroll
    for (int o = 1; o <= 2; o <<= 1) {
        mx0 = fmaxf(mx0, __shfl_xor_sync(0xffffffffu, mx0, o));
        mx1 = fmaxf(mx1, __shfl_xor_sync(0xffffffffu, mx1, o));
    }
    const float mn0 = fmaxf(m[0], mx0), mn1 = fmaxf(m[1], mx1);
    const float c0 = __expf(m[0] - mn0), c1 = __expf(m[1] - mn1);
    m[0] = mn0; m[1] = mn1;
    float s0 = 0.f, s1 = 0.f;
#pragma unroll
    for (int ni = 0; ni < 8; ++ni) {
        const float p0 = __expf(S[ni][0] - mn0), p1 = __expf(S[ni][1] - mn0);
        const float p2 = __expf(S[ni][2] - mn1), p3 = __expf(S[ni][3] - mn1);
        s0 += p0 + p1; s1 += p2 + p3;
        const int sc = ni * 8 + 2 * t;
        sP[(sc    ) * AST + warpM + g    ] = f2tf32(p0);
        sP[(sc + 1) * AST + warpM + g    ] = f2tf32(p1);
        sP[(sc    ) * AST + warpM + g + 8] = f2tf32(p2);
        sP[(sc + 1) * AST + warpM + g + 8] = f2tf32(p3);
        O[ni][0] *= c0; O[ni][1] *= c0; O[ni][2] *= c1; O[ni][3] *= c1;
    }
#pragma unroll
    for (int o = 1; o <= 2; o <<= 1) {
        s0 += __shfl_xor_sync(0xffffffffu, s0, o);
        s1 += __shfl_xor_sync(0xffffffffu, s1, o);
    }
    l[0] = l[0] * c0 + s0;
    l[1] = l[1] * c1 + s1;
}

__global__ __launch_bounds__(128) void attn_kernel(const float* __restrict__ fused,
                                                   const float* __restrict__ rl,
                                                   const float* __restrict__ jwg,
                                                   const float* __restrict__ gate,
                                                   const float* __restrict__ inc,
                                                   float* __restrict__ comb)
{
    extern __shared__ uint32_t sm[];
    uint32_t* sK   = sm;                // [d][s] 64xAST (aliased by P [s][q] after QK)
    uint32_t* sKlo = sK   + 64 * AST;   // [d][s]
    uint32_t* sV   = sKlo + 64 * AST;   // [s][d]
    uint32_t* sGV  = sV   + 64 * AST;   // [s][d]
    uint32_t* sJWh = sGV  + 64 * AST;   // [i][s] 8xAST (rows 6,7 zero)
    uint32_t* sJWl = sJWh + 8 * AST;    // [i][s] 8xAST (rows 6,7 zero)
    uint32_t* sP   = sK;                // alias

    const int h = blockIdx.y;
    const int qb = gridDim.x - 1 - blockIdx.x;  // heavy tiles first
    const int qt0 = qb * 64;
    const int tid = threadIdx.x;
    const int lane = tid & 31, w = tid >> 5;
    const int g = lane >> 2, t = lane & 3;
    const int warpM = w * 16;
    const int lr = tid >> 1, d0 = (tid & 1) * 32;

    for (int i = tid; i < 2 * AST; i += 128) { sJWh[6 * AST + i] = 0; sJWl[6 * AST + i] = 0; }

    // ---- Q fragments (hi/lo) in registers, loaded straight from global ----
    uint32_t qh[8][4], ql[8][4];
    {
        const float* q0 = fused + (size_t)(qt0 + warpM + g) * FD + h * DHH;
        const float* q1 = q0 + (size_t)8 * FD;
#pragma unroll
        for (int k8 = 0; k8 < 8; ++k8) {
            const int kk = k8 * 8 + t;
            const float v0 = q0[kk], v1 = q1[kk], v2 = q0[kk + 4], v3 = q1[kk + 4];
            qh[k8][0] = f2tf32(v0); ql[k8][0] = f2tf32(v0 - __uint_as_float(qh[k8][0]));
            qh[k8][1] = f2tf32(v1); ql[k8][1] = f2tf32(v1 - __uint_as_float(qh[k8][1]));
            qh[k8][2] = f2tf32(v2); ql[k8][2] = f2tf32(v2 - __uint_as_float(qh[k8][2]));
            qh[k8][3] = f2tf32(v3); ql[k8][3] = f2tf32(v3 - __uint_as_float(qh[k8][3]));
        }
    }
    // ---- RL fragments (hi/lo) in registers ----
    uint32_t rlh[4], rll[4];
    {
        const float* r0p = rl + (size_t)(qt0 + warpM + g) * (NH * 6) + h * 6;
        const float* r1p = r0p + (size_t)8 * (NH * 6);
        const float v0 = r0p[t], v1 = r1p[t];
        const float v2 = (t < 2) ? r0p[t + 4] : 0.f;
        const float v3 = (t < 2) ? r1p[t + 4] : 0.f;
        rlh[0] = f2tf32(v0); rll[0] = f2tf32(v0 - __uint_as_float(rlh[0]));
        rlh[1] = f2tf32(v1); rll[1] = f2tf32(v1 - __uint_as_float(rlh[1]));
        rlh[2] = f2tf32(v2); rll[2] = f2tf32(v2 - __uint_as_float(rlh[2]));
        rlh[3] = f2tf32(v3); rll[3] = f2tf32(v3 - __uint_as_float(rlh[3]));
    }
    const float iscale = inc[h];

    float Os[8][4] = {}, Og[8][4] = {};
    float ms[2] = {-1e30f, -1e30f}, mg[2] = {-1e30f, -1e30f}, ls[2] = {}, lg[2] = {};

    for (int kt0 = 0; kt0 <= qt0; kt0 += 64) {
        __syncthreads();   // prior-iter sP/sGV reads done before tile overwrite
        { // load K hi/lo (transposed), V/GV natural, JW hi/lo
            const float* ksrc = fused + (size_t)(kt0 + lr) * FD +  DD + h * DHH + d0;
            const float* vsrc = fused + (size_t)(kt0 + lr) * FD + 2 * DD + h * DHH + d0;
            const float* gsrc = fused + (size_t)(kt0 + lr) * FD + 3 * DD + h * DHH + d0;
#pragma unroll
            for (int u = 0; u < 8; ++u) {
                const int d = d0 + 4 * u;
                const float4 kv = *(const float4*)(ksrc + 4 * u);
                uint32_t h0 = f2tf32(kv.x), h1 = f2tf32(kv.y), h2 = f2tf32(kv.z), h3 = f2tf32(kv.w);
                sK[(d + 0) * AST + lr] = h0;
                sK[(d + 1) * AST + lr] = h1;
                sK[(d + 2) * AST + lr] = h2;
                sK[(d + 3) * AST + lr] = h3;
                sKlo[(d + 0) * AST + lr] = f2tf32(kv.x - __uint_as_float(h0));
                sKlo[(d + 1) * AST + lr] = f2tf32(kv.y - __uint_as_float(h1));
                sKlo[(d + 2) * AST + lr] = f2tf32(kv.z - __uint_as_float(h2));
                sKlo[(d + 3) * AST + lr] = f2tf32(kv.w - __uint_as_float(h3));
                const float4 vv = *(const float4*)(vsrc + 4 * u);
                uint4 pv; pv.x = f2tf32(vv.x); pv.y = f2tf32(vv.y);
                pv.z = f2tf32(vv.z); pv.w = f2tf32(vv.w);
                *(uint4*)&sV[lr * AST + d] = pv;
                const float4 gv = *(const float4*)(gsrc + 4 * u);
                uint4 pg; pg.x = f2tf32(gv.x); pg.y = f2tf32(gv.y);
                pg.z = f2tf32(gv.z); pg.w = f2tf32(gv.w);
                *(uint4*)&sGV[lr * AST + d] = pg;
            }
        }
        if (tid < 64) {
#pragma unroll
            for (int i = 0; i < 6; ++i) {
                const float v = jwg[(size_t)(kt0 + tid) * (NH * 6) + h * 6 + i];
                const uint32_t hi = f2tf32(v);
                sJWh[i * AST + tid] = hi;
                sJWl[i * AST + tid] = f2tf32(v - __uint_as_float(hi));
            }
        }
        __syncthreads();
        const bool diag = (kt0 == qt0);

        // ==== std path: S = Q K^T * 1/8 (3-term split tf32) ====
        float S[8][4] = {};
#pragma unroll
        for (int k8 = 0; k8 < 8; ++k8) {
            const int kk = k8 * 8 + t;
#pragma unroll
            for (int ni = 0; ni < 8; ++ni) {
                const int c = ni * 8 + g;
                uint32_t bh[2], bl[2];
                bh[0] = sK[kk * AST + c];
                bh[1] = sK[(kk + 4) * AST + c];
                bl[0] = sKlo[kk * AST + c];
                bl[1] = sKlo[(kk + 4) * AST + c];
                mma_tf32(S[ni], qh[k8], bh);
                mma_tf32(S[ni], ql[k8], bh);
                mma_tf32(S[ni], qh[k8], bl);
            }
        }
#pragma unroll
        for (int ni = 0; ni < 8; ++ni) {
            const int sc = ni * 8 + 2 * t;
#pragma unroll
            for (int j = 0; j < 4; ++j) S[ni][j] *= 0.125f;
            if (diag) {
                const int r0 = warpM + g, r1 = r0 + 8;
                if (sc     > r0) S[ni][0] = -1e30f;
                if (sc + 1 > r0) S[ni][1] = -1e30f;
                if (sc     > r1) S[ni][2] = -1e30f;
                if (sc + 1 > r1) S[ni][3] = -1e30f;
            }
        }
        __syncthreads();   // all warps done reading sK/sKlo before P overwrites sK
        softmax_update_mma(S, ms, ls, Os, sP, warpM, g, t);
        __syncwarp();
#pragma unroll
        for (int k8 = 0; k8 < 8; ++k8) {
            const int kk = k8 * 8 + t;
            uint32_t a[4], b[2];
            a[0] = sP[kk * AST + warpM + g];
            a[1] = sP[kk * AST + warpM + g + 8];
            a[2] = sP[(kk + 4) * AST + warpM + g];
            a[3] = sP[(kk + 4) * AST + warpM + g + 8];
#pragma unroll
            for (int ni = 0; ni < 8; ++ni) {
                b[0] = sV[kk * AST + ni * 8 + g];
                b[1] = sV[(kk + 4) * AST + ni * 8 + g];
                mma_tf32(Os[ni], a, b);
            }
        }
        __syncwarp();

        // ==== geo path: S = RL . JW * inc_scale (3-term split, k=8 padded) ====
#pragma unroll
        for (int ni = 0; ni < 8; ++ni)
#pragma unroll
            for (int j = 0; j < 4; ++j) S[ni][j] = 0.f;
#pragma unroll
        for (int ni = 0; ni < 8; ++ni) {
            const int c = ni * 8 + g;
            uint32_t bh[2], bl[2];
            bh[0] = sJWh[t * AST + c];
            bh[1] = sJWh[(t + 4) * AST + c];
            bl[0] = sJWl[t * AST + c];
            bl[1] = sJWl[(t + 4) * AST + c];
            mma_tf32(S[ni], rlh, bh);
            mma_tf32(S[ni], rll, bh);
            mma_tf32(S[ni], rlh, bl);
        }
#pragma unroll
        for (int ni = 0; ni < 8; ++ni) {
            const int sc = ni * 8 + 2 * t;
#pragma unroll
            for (int j = 0; j < 4; ++j) S[ni][j] *= iscale;
            if (diag) {
                const int r0 = warpM + g, r1 = r0 + 8;
                if (sc     > r0) S[ni][0] = -1e30f;
                if (sc + 1 > r0) S[ni][1] = -1e30f;
                if (sc     > r1) S[ni][2] = -1e30f;
                if (sc + 1 > r1) S[ni][3] = -1e30f;
            }
        }
        // P region writes are warp-column-private from here on: no block barrier
        softmax_update_mma(S, mg, lg, Og, sP, warpM, g, t);
        __syncwarp();
#pragma unroll
        for (int k8 = 0; k8 < 8; ++k8) {
            const int kk = k8 * 8 + t;
            uint32_t a[4], b[2];
            a[0] = sP[kk * AST + warpM + g];
            a[1] = sP[kk * AST + warpM + g + 8];
            a[2] = sP[(kk + 4) * AST + warpM + g];
            a[3] = sP[(kk + 4) * AST + warpM + g + 8];
#pragma unroll
            for (int ni = 0; ni < 8; ++ni) {
                b[0] = sGV[kk * AST + ni * 8 + g];
                b[1] = sGV[(kk + 4) * AST + ni * 8 + g];
                mma_tf32(Og[ni], a, b);
            }
        }
        __syncwarp();
    }

    // ---- finalize: combined = (1-g)*std/ls + g*geo/lg ----
    const int r0 = qt0 + warpM + g, r1 = r0 + 8;
    const float g0 = gate[r0], g1 = gate[r1];
    const float as0 = (1.f - g0) / ls[0], ag0 = g0 / lg[0];
    const float as1 = (1.f - g1) / ls[1], ag1 = g1 / lg[1];
#pragma unroll
    for (int ni = 0; ni < 8; ++ni) {
        const int d = ni * 8 + 2 * t;
        float2 o0 = make_float2(Os[ni][0] * as0 + Og[ni][0] * ag0,
                                Os[ni][1] * as0 + Og[ni][1] * ag0);
        float2 o1 = make_float2(Os[ni][2] * as1 + Og[ni][2] * ag1,
                                Os[ni][3] * as1 + Og[ni][3] * ag1);
        *(float2*)&comb[(size_t)r0 * DD + h * DHH + d] = o0;
        *(float2*)&comb[(size_t)r1 * DD + h * DHH + d] = o1;
    }
}

// ---------------- host ----------------
extern "C" void kernel_launch(void* const* d_in, const int* in_sizes, int n_in,
                              void* d_out, int out_size)
{
    (void)in_sizes; (void)n_in; (void)out_size;
    const float* x     = (const float*)d_in[0];
    const float* ln1g  = (const float*)d_in[1];
    const float* ln1b  = (const float*)d_in[2];
    const float* qkvw  = (const float*)d_in[3];
    const float* qkvb  = (const float*)d_in[4];
    const float* w1w   = (const float*)d_in[5];
    const float* w2w   = (const float*)d_in[6];
    const float* w1r   = (const float*)d_in[7];
    const float* w2r   = (const float*)d_in[8];
    const float* geovw = (const float*)d_in[9];
    const float* geovb = (const float*)d_in[10];
    const float* gatew = (const float*)d_in[11];
    const float* gateb = (const float*)d_in[12];
    const float* incs  = (const float*)d_in[13];
    const float* outw  = (const float*)d_in[14];
    const float* outb  = (const float*)d_in[15];
    const float* ln2g  = (const float*)d_in[16];
    const float* ln2b  = (const float*)d_in[17];
    const float* fcw   = (const float*)d_in[18];
    const float* fcb   = (const float*)d_in[19];
    const float* projw = (const float*)d_in[20];
    const float* projb = (const float*)d_in[21];
    float* out = (float*)d_out;

    float *xn, *fz, *wp, *bp, *rlp, *jwp, *gatep, *combp, *hp, *mp, *actp, *partp;
    cudaGetSymbolAddress((void**)&xn,    g_xn);
    cudaGetSymbolAddress((void**)&fz,    g_fused);
    cudaGetSymbolAddress((void**)&wp,    g_wpack);
    cudaGetSymbolAddress((void**)&bp,    g_bpack);
    cudaGetSymbolAddress((void**)&rlp,   g_rl);
    cudaGetSymbolAddress((void**)&jwp,   g_jw);
    cudaGetSymbolAddress((void**)&gatep, g_gate);
    cudaGetSymbolAddress((void**)&combp, g_comb);
    cudaGetSymbolAddress((void**)&hp,    g_h);
    cudaGetSymbolAddress((void**)&mp,    g_m);
    cudaGetSymbolAddress((void**)&actp,  g_act);
    cudaGetSymbolAddress((void**)&partp, g_part);

    const int smem_attn = (4 * 64 * AST + 2 * 8 * AST) * (int)sizeof(uint32_t);
    cudaFuncSetAttribute(attn_kernel, cudaFuncAttributeMaxDynamicSharedMemorySize, smem_attn);
    cudaFuncSetAttribute(gemm_tf32<false>, cudaFuncAttributeMaxDynamicSharedMemorySize, GSMEM);
    cudaFuncSetAttribute(gemm_tf32<true>,  cudaFuncAttributeMaxDynamicSharedMemorySize, GSMEM);
    cudaFuncSetAttribute(gemm_tf32_part,   cudaFuncAttributeMaxDynamicSharedMemorySize, GSMEM);

    // 1. xn = LN1(x)
    ln_kernel<<<TT, 256>>>(x, ln1g, ln1b, xn);
    // 2. pack fused weights + bias
    pack_kernel<<<(DD * FD + 255) / 256, 256>>>(qkvw, geovw, w1w, w2w, w1r, w2r, gatew,
                                                qkvb, geovb, wp, bp);
    // 3. fused = xn @ [qkv_w | geov_w | wcat] + bias   (2048 x 3328 x 768)
    gemm_tf32<false><<<dim3(26, 16), 256, GSMEM>>>(xn, wp, bp, fz, TT, FD, DD);
    // 4. exterior lines + J + gate
    lines_kernel<<<(TT * NH + 255) / 256, 256>>>(fz, gateb, rlp, jwp, gatep);
    // 5. fused dual-path attention -> combined
    attn_kernel<<<dim3(32, NH), 128, smem_attn>>>(fz, rlp, jwp, gatep, incs, combp);
    // 6. h = x + combined @ out_w + b  (split-K 2, 2-pass deterministic)
    gemm_tf32_part<<<dim3(6, 16, 2), 256, GSMEM>>>(combp, outw, partp, TT, DD, DD, 384);
    reduce_kernel<2><<<TT * DD / 4 / 256, 256>>>(partp, outb, x, hp);
    // 7. m = LN2(h)
    ln_kernel<<<TT, 256>>>(hp, ln2g, ln2b, mp);
    // 8. act = gelu(m @ fc_w + b)
    gemm_tf32<true><<<dim3(24, 16), 256, GSMEM>>>(mp, fcw, fcb, actp, TT, 4 * DD, DD);
    // 9. out = h + act @ proj_w + b  (split-K 4, 2-pass deterministic)
    gemm_tf32_part<<<dim3(6, 16, 4), 256, GSMEM>>>(actp, projw, partp, TT, DD, 4 * DD, 768);
    reduce_kernel<4><<<TT * DD / 4 / 256, 256>>>(partp, projb, hp, out);
}